// round 1
// baseline (speedup 1.0000x reference)
#include <cuda_runtime.h>

#define Nn    100000
#define Ee    800000
#define INF   256
#define HIDD  64
#define HD    128     // HID*HEADS
#define CC    40
#define EPSL  1e-5f

// ---------------- scratch (device globals; no allocation allowed) ----------------
__device__ float g_h[Nn * HIDD];
__device__ float g_prev[Nn * HIDD];
__device__ float g_q[Nn * HD];
__device__ float g_k[Nn * HD];
__device__ float g_v[Nn * HD];
__device__ float g_out[Nn * HD];
__device__ float g_rsq[Nn];
__device__ float g_kvs[2 * HIDD * HIDD];   // [head][m][d]
__device__ float g_sumK[HD];
__device__ float g_sumV[HD];
__device__ float g_sums[2];                // {sum q^2, sum k^2}

// ---------------- fc0 GEMM + bias + LN + ReLU ----------------
// out tile: 64 rows x 64 cols per block, 256 threads, 4x4 per thread.
__global__ void k_fc0(const float* __restrict__ x, const float* __restrict__ w,
                      const float* __restrict__ bias, const float* __restrict__ lnw,
                      const float* __restrict__ lnb) {
    __shared__ float xs[64][68];  // transposed: xs[k][r]
    __shared__ float ws[64][68];  // ws[k][c]
    int tid = threadIdx.x;
    int tx = tid & 15, ty = tid >> 4;
    int row0 = blockIdx.x * 64;
    float acc[4][4] = {};
    for (int kc = 0; kc < 4; kc++) {
        __syncthreads();
#pragma unroll
        for (int l = 0; l < 4; l++) {
            int lin = tid + l * 256;      // 1024 float4 slots
            int r = lin >> 4, c4 = lin & 15;
            int gr = row0 + r; if (gr >= Nn) gr = Nn - 1;
            float4 v = *(const float4*)&x[(size_t)gr * INF + kc * 64 + c4 * 4];
            xs[c4 * 4 + 0][r] = v.x; xs[c4 * 4 + 1][r] = v.y;
            xs[c4 * 4 + 2][r] = v.z; xs[c4 * 4 + 3][r] = v.w;
            float4 wv = *(const float4*)&w[(size_t)(kc * 64 + r) * HIDD + c4 * 4];
            *(float4*)&ws[r][c4 * 4] = wv;
        }
        __syncthreads();
#pragma unroll
        for (int kk = 0; kk < 64; kk++) {
            float4 a4 = *(const float4*)&xs[kk][ty * 4];
            float4 b4 = *(const float4*)&ws[kk][tx * 4];
            float a_[4] = {a4.x, a4.y, a4.z, a4.w};
            float b_[4] = {b4.x, b4.y, b4.z, b4.w};
#pragma unroll
            for (int i = 0; i < 4; i++)
#pragma unroll
                for (int j = 0; j < 4; j++) acc[i][j] += a_[i] * b_[j];
        }
    }
    float lw[4], lb[4], bb[4];
#pragma unroll
    for (int j = 0; j < 4; j++) {
        int c = tx * 4 + j;
        bb[j] = bias[c]; lw[j] = lnw[c]; lb[j] = lnb[c];
    }
#pragma unroll
    for (int i = 0; i < 4; i++) {
        float s = 0.f, sq = 0.f;
#pragma unroll
        for (int j = 0; j < 4; j++) {
            float v = acc[i][j] + bb[j];
            acc[i][j] = v; s += v; sq += v * v;
        }
        for (int m = 1; m < 16; m <<= 1) {
            s += __shfl_xor_sync(0xffffffffu, s, m);
            sq += __shfl_xor_sync(0xffffffffu, sq, m);
        }
        float mu = s * 0.015625f;
        float var = sq * 0.015625f - mu * mu;
        float rs = rsqrtf(var + EPSL);
        int gr = row0 + ty * 4 + i;
        if (gr < Nn) {
#pragma unroll
            for (int j = 0; j < 4; j++) {
                float v = (acc[i][j] - mu) * rs * lw[j] + lb[j];
                v = fmaxf(v, 0.f);
                g_h[(size_t)gr * HIDD + tx * 4 + j] = v;
                g_prev[(size_t)gr * HIDD + tx * 4 + j] = v;
            }
        }
    }
}

// ---------------- degree kernels ----------------
__global__ void k_zero_deg() {
    int i = blockIdx.x * blockDim.x + threadIdx.x;
    if (i < Nn) g_rsq[i] = 0.f;
}
__global__ void k_hist(const int* __restrict__ col) {
    int i = blockIdx.x * blockDim.x + threadIdx.x;
    if (i < Ee) atomicAdd(&g_rsq[col[i]], 1.0f);
}
__global__ void k_rsq() {
    int i = blockIdx.x * blockDim.x + threadIdx.x;
    if (i < Nn) {
        float d = g_rsq[i];
        g_rsq[i] = d > 0.f ? rsqrtf(d) : 0.f;
    }
}

// ---------------- zero per-layer reduction scratch ----------------
__global__ void k_zero_red() {
    int i = blockIdx.x * blockDim.x + threadIdx.x;
    int stride = gridDim.x * blockDim.x;
    for (int j = i; j < 8192; j += stride) g_kvs[j] = 0.f;
    if (i < HD) { g_sumK[i] = 0.f; g_sumV[i] = 0.f; }
    if (i < 2) g_sums[i] = 0.f;
}

// ---------------- QKV GEMM + fused reductions ----------------
__global__ void k_qkv(const float* __restrict__ Wq, const float* __restrict__ Wk,
                      const float* __restrict__ Wv, const float* __restrict__ bq,
                      const float* __restrict__ bk, const float* __restrict__ bv) {
    __shared__ float hs[64][68];        // transposed h: hs[k][r]
    __shared__ float ws[64][68];        // ws[k][c]
    __shared__ float red[16][16][4];    // [ty][tx][j]
    int tid = threadIdx.x;
    int tx = tid & 15, ty = tid >> 4;
    int row0 = blockIdx.x * 64;
#pragma unroll
    for (int l = 0; l < 4; l++) {
        int lin = tid + l * 256;
        int r = lin >> 4, c4 = lin & 15;
        int gr = row0 + r;
        float4 v = make_float4(0.f, 0.f, 0.f, 0.f);
        if (gr < Nn) v = *(const float4*)&g_h[(size_t)gr * HIDD + c4 * 4];
        hs[c4 * 4 + 0][r] = v.x; hs[c4 * 4 + 1][r] = v.y;
        hs[c4 * 4 + 2][r] = v.z; hs[c4 * 4 + 3][r] = v.w;
    }
    bool rowok[4];
#pragma unroll
    for (int i = 0; i < 4; i++) rowok[i] = (row0 + ty * 4 + i) < Nn;
    float q2 = 0.f, k2 = 0.f;
    for (int mat = 0; mat < 3; mat++) {
        const float* W = (mat == 0) ? Wq : ((mat == 1) ? Wk : Wv);
        const float* B = (mat == 0) ? bq : ((mat == 1) ? bk : bv);
        float* dst = (mat == 0) ? g_q : ((mat == 1) ? g_k : g_v);
        for (int cc = 0; cc < 2; cc++) {
            __syncthreads();
#pragma unroll
            for (int l = 0; l < 4; l++) {
                int lin = tid + l * 256;
                int kk = lin >> 4, c4 = lin & 15;
                float4 wv = *(const float4*)&W[(size_t)kk * HD + cc * 64 + c4 * 4];
                *(float4*)&ws[kk][c4 * 4] = wv;
            }
            __syncthreads();
            float acc[4][4] = {};
#pragma unroll
            for (int kk = 0; kk < 64; kk++) {
                float4 a4 = *(const float4*)&hs[kk][ty * 4];
                float4 b4 = *(const float4*)&ws[kk][tx * 4];
                float a_[4] = {a4.x, a4.y, a4.z, a4.w};
                float b_[4] = {b4.x, b4.y, b4.z, b4.w};
#pragma unroll
                for (int i = 0; i < 4; i++)
#pragma unroll
                    for (int j = 0; j < 4; j++) acc[i][j] += a_[i] * b_[j];
            }
            float part[4] = {0.f, 0.f, 0.f, 0.f};
#pragma unroll
            for (int i = 0; i < 4; i++) {
#pragma unroll
                for (int j = 0; j < 4; j++) {
                    int c = cc * 64 + tx * 4 + j;
                    float v = acc[i][j] + B[c];
                    if (!rowok[i]) v = 0.f;
                    else dst[(size_t)(row0 + ty * 4 + i) * HD + c] = v;
                    if (mat == 0) q2 += v * v;
                    if (mat == 1) { k2 += v * v; part[j] += v; }
                    if (mat == 2) part[j] += v;
                }
            }
            if (mat >= 1) {
#pragma unroll
                for (int j = 0; j < 4; j++) red[ty][tx][j] = part[j];
                __syncthreads();
                if (tid < 64) {
                    int c = tid, txo = c >> 2, j = c & 3;
                    float s = 0.f;
#pragma unroll
                    for (int t2 = 0; t2 < 16; t2++) s += red[t2][txo][j];
                    if (mat == 1) atomicAdd(&g_sumK[cc * 64 + c], s);
                    else          atomicAdd(&g_sumV[cc * 64 + c], s);
                }
            }
        }
    }
    for (int m = 1; m < 32; m <<= 1) {
        q2 += __shfl_xor_sync(0xffffffffu, q2, m);
        k2 += __shfl_xor_sync(0xffffffffu, k2, m);
    }
    if ((tid & 31) == 0) {
        atomicAdd(&g_sums[0], q2);
        atomicAdd(&g_sums[1], k2);
    }
}

// ---------------- kvs = sum_n k[n,h,m] * v[n,h,d] ----------------
__global__ void k_reduce() {
    __shared__ float ks[32][132];
    __shared__ float vs[32][132];
    int tid = threadIdx.x;
    int hh = tid >> 7, u = tid & 127;
    int m0 = (u & 15) * 4, d0 = (u >> 4) * 8;
    float acc[4][8] = {};
    int ntiles = (Nn + 31) / 32;
    for (int t = blockIdx.x; t < ntiles; t += gridDim.x) {
        __syncthreads();
#pragma unroll
        for (int l = 0; l < 4; l++) {
            int lin = tid + l * 256;
            int nl = lin >> 5, c4 = lin & 31;
            int n = t * 32 + nl;
            float4 kv4 = make_float4(0.f, 0.f, 0.f, 0.f), vv4 = kv4;
            if (n < Nn) {
                kv4 = *(const float4*)&g_k[(size_t)n * HD + c4 * 4];
                vv4 = *(const float4*)&g_v[(size_t)n * HD + c4 * 4];
            }
            *(float4*)&ks[nl][c4 * 4] = kv4;
            *(float4*)&vs[nl][c4 * 4] = vv4;
        }
        __syncthreads();
#pragma unroll 4
        for (int nn = 0; nn < 32; nn++) {
            float4 k4 = *(const float4*)&ks[nn][hh * 64 + m0];
            float4 va = *(const float4*)&vs[nn][hh * 64 + d0];
            float4 vb = *(const float4*)&vs[nn][hh * 64 + d0 + 4];
            float kk_[4] = {k4.x, k4.y, k4.z, k4.w};
            float vv_[8] = {va.x, va.y, va.z, va.w, vb.x, vb.y, vb.z, vb.w};
#pragma unroll
            for (int mm = 0; mm < 4; mm++)
#pragma unroll
                for (int dd = 0; dd < 8; dd++) acc[mm][dd] += kk_[mm] * vv_[dd];
        }
    }
#pragma unroll
    for (int mm = 0; mm < 4; mm++)
#pragma unroll
        for (int dd = 0; dd < 8; dd++)
            atomicAdd(&g_kvs[hh * 4096 + (m0 + mm) * 64 + d0 + dd], acc[mm][dd]);
}

// ---------------- attention output: out = (q@kvs*s + sumV) / (q.sumK*s + N) ----------------
__global__ void k_attn() {
    __shared__ float kv[64][68];     // kv[m][d]
    __shared__ float qs[64][68];     // transposed q: qs[m][r]
    __shared__ float sumK_s[64], sumV_s[64], den[64];
    int tid = threadIdx.x;
    int tx = tid & 15, ty = tid >> 4;
    int row0 = blockIdx.x * 64;
    float sc = rsqrtf(g_sums[0] * g_sums[1]);
    for (int h = 0; h < 2; h++) {
        __syncthreads();
#pragma unroll
        for (int l = 0; l < 4; l++) {
            int lin = tid + l * 256;
            int r = lin >> 4, c4 = lin & 15;
            float4 kvv = *(const float4*)&g_kvs[h * 4096 + r * 64 + c4 * 4];
            *(float4*)&kv[r][c4 * 4] = kvv;
            int gr = row0 + r;
            float4 qv = make_float4(0.f, 0.f, 0.f, 0.f);
            if (gr < Nn) qv = *(const float4*)&g_q[(size_t)gr * HD + h * 64 + c4 * 4];
            qs[c4 * 4 + 0][r] = qv.x; qs[c4 * 4 + 1][r] = qv.y;
            qs[c4 * 4 + 2][r] = qv.z; qs[c4 * 4 + 3][r] = qv.w;
        }
        if (tid < 64) {
            sumK_s[tid] = g_sumK[h * 64 + tid];
            sumV_s[tid] = g_sumV[h * 64 + tid];
        }
        __syncthreads();
        if (tid < 64) {
            float a = 0.f;
#pragma unroll
            for (int m = 0; m < 64; m++) a += qs[m][tid] * sumK_s[m];
            den[tid] = a * sc + 100000.0f;
        }
        __syncthreads();
        float acc[4][4] = {};
#pragma unroll
        for (int kk = 0; kk < 64; kk++) {
            float4 a4 = *(const float4*)&qs[kk][ty * 4];
            float4 b4 = *(const float4*)&kv[kk][tx * 4];
            float a_[4] = {a4.x, a4.y, a4.z, a4.w};
            float b_[4] = {b4.x, b4.y, b4.z, b4.w};
#pragma unroll
            for (int i = 0; i < 4; i++)
#pragma unroll
                for (int j = 0; j < 4; j++) acc[i][j] += a_[i] * b_[j];
        }
#pragma unroll
        for (int i = 0; i < 4; i++) {
            int gr = row0 + ty * 4 + i;
            if (gr < Nn) {
                float dn = den[ty * 4 + i];
#pragma unroll
                for (int j = 0; j < 4; j++) {
                    int d = tx * 4 + j;
                    float num = acc[i][j] * sc + sumV_s[d];
                    g_out[(size_t)gr * HD + h * 64 + d] = num / dn;
                }
            }
        }
    }
}

// ---------------- GCN scatter: out[col] += rsq[row]*rsq[col] * v[row] ----------------
__global__ void k_gcn(const int* __restrict__ row, const int* __restrict__ col) {
    int lane = threadIdx.x & 31;
    int warp = (blockIdx.x * blockDim.x + threadIdx.x) >> 5;
    int nwarp = (gridDim.x * blockDim.x) >> 5;
    for (int e = warp; e < Ee; e += nwarp) {
        int r = 0, c = 0; float w = 0.f;
        if (lane == 0) {
            r = row[e]; c = col[e];
            w = g_rsq[r] * g_rsq[c];
        }
        r = __shfl_sync(0xffffffffu, r, 0);
        c = __shfl_sync(0xffffffffu, c, 0);
        w = __shfl_sync(0xffffffffu, w, 0);
        float4 v = *(const float4*)&g_v[(size_t)r * HD + lane * 4];
        float* dst = &g_out[(size_t)c * HD + lane * 4];
        asm volatile("red.global.add.v4.f32 [%0], {%1,%2,%3,%4};"
                     :: "l"(dst), "f"(v.x * w), "f"(v.y * w), "f"(v.z * w), "f"(v.w * w)
                     : "memory");
    }
}

// ---------------- head-mean + residual + LN ----------------
__global__ void k_combine(const float* __restrict__ lnw, const float* __restrict__ lnb) {
    int warp = threadIdx.x >> 5, lane = threadIdx.x & 31;
    int n = blockIdx.x * 8 + warp;
    if (n >= Nn) return;
    float hv[2];
#pragma unroll
    for (int p = 0; p < 2; p++) {
        int d = lane + p * 32;
        float o = 0.5f * (g_out[(size_t)n * HD + d] + g_out[(size_t)n * HD + 64 + d]);
        hv[p] = 0.5f * o + 0.5f * g_prev[(size_t)n * HIDD + d];
    }
    float s = hv[0] + hv[1];
    float sq = hv[0] * hv[0] + hv[1] * hv[1];
    for (int m = 1; m < 32; m <<= 1) {
        s += __shfl_xor_sync(0xffffffffu, s, m);
        sq += __shfl_xor_sync(0xffffffffu, sq, m);
    }
    float mu = s * 0.015625f;
    float var = sq * 0.015625f - mu * mu;
    float rs = rsqrtf(var + EPSL);
#pragma unroll
    for (int p = 0; p < 2; p++) {
        int d = lane + p * 32;
        float y = (hv[p] - mu) * rs * lnw[d] + lnb[d];
        g_h[(size_t)n * HIDD + d] = y;
        g_prev[(size_t)n * HIDD + d] = y;
    }
}

// ---------------- final projection ----------------
__global__ void k_fco(const float* __restrict__ w, const float* __restrict__ b,
                      float* __restrict__ out) {
    __shared__ float ws[64][40];
    __shared__ float hs[64][65];
    int tid = threadIdx.x;
    int row0 = blockIdx.x * 64;
    for (int l = tid; l < 64 * 40; l += 256) ws[l / 40][l % 40] = w[l];
#pragma unroll
    for (int l = 0; l < 4; l++) {
        int lin = tid + l * 256;
        int r = lin >> 4, c4 = lin & 15;
        int gr = row0 + r; if (gr >= Nn) gr = Nn - 1;
        float4 v = *(const float4*)&g_h[(size_t)gr * HIDD + c4 * 4];
        hs[r][c4 * 4 + 0] = v.x; hs[r][c4 * 4 + 1] = v.y;
        hs[r][c4 * 4 + 2] = v.z; hs[r][c4 * 4 + 3] = v.w;
    }
    __syncthreads();
    int r = tid & 63, cg = tid >> 6;
    float acc[10] = {};
#pragma unroll
    for (int kk = 0; kk < 64; kk++) {
        float a = hs[r][kk];
        const float* wr = &ws[kk][cg * 10];
#pragma unroll
        for (int j = 0; j < 10; j++) acc[j] += a * wr[j];
    }
    int gr = row0 + r;
    if (gr < Nn) {
#pragma unroll
        for (int j = 0; j < 10; j++)
            out[(size_t)gr * CC + cg * 10 + j] = acc[j] + b[cg * 10 + j];
    }
}

// ---------------- launcher ----------------
extern "C" void kernel_launch(void* const* d_in, const int* in_sizes, int n_in,
                              void* d_out, int out_size) {
    (void)in_sizes; (void)n_in; (void)out_size;
    const float* x     = (const float*)d_in[0];
    const int*   ei    = (const int*)d_in[1];
    const float* fc0_w = (const float*)d_in[2];
    const float* fc0_b = (const float*)d_in[3];
    const float* ln_w  = (const float*)d_in[4];
    const float* ln_b  = (const float*)d_in[5];
    const float* Wq    = (const float*)d_in[6];
    const float* Wk    = (const float*)d_in[7];
    const float* Wv    = (const float*)d_in[8];
    const float* bq    = (const float*)d_in[9];
    const float* bk    = (const float*)d_in[10];
    const float* bv    = (const float*)d_in[11];
    const float* fco_w = (const float*)d_in[12];
    const float* fco_b = (const float*)d_in[13];
    float* out = (float*)d_out;

    const int GB = (Nn + 63) / 64;   // 1563 row-tile blocks

    k_fc0<<<GB, 256>>>(x, fc0_w, fc0_b, ln_w, ln_b);
    k_zero_deg<<<(Nn + 255) / 256, 256>>>();
    k_hist<<<(Ee + 255) / 256, 256>>>(ei + Ee);
    k_rsq<<<(Nn + 255) / 256, 256>>>();

    for (int l = 0; l < 2; l++) {
        k_zero_red<<<34, 256>>>();
        k_qkv<<<GB, 256>>>(Wq + (size_t)l * HIDD * HD, Wk + (size_t)l * HIDD * HD,
                           Wv + (size_t)l * HIDD * HD,
                           bq + l * HD, bk + l * HD, bv + l * HD);
        k_reduce<<<256, 256>>>();
        k_attn<<<GB, 256>>>();
        k_gcn<<<1184, 256>>>(ei, ei + Ee);
        k_combine<<<(Nn + 7) / 8, 256>>>(ln_w + (l + 1) * HIDD, ln_b + (l + 1) * HIDD);
    }
    k_fco<<<GB, 256>>>(fco_w, fco_b, out);
}

// round 2
// speedup vs baseline: 1.0538x; 1.0538x over previous
#include <cuda_runtime.h>

#define Nn    100000
#define Ee    800000
#define INF   256
#define HIDD  64
#define HD    128
#define CC    40
#define EPSL  1e-5f
#define FULL  0xffffffffu

// ---------------- scratch ----------------
__device__ float g_h[Nn * HIDD];
__device__ float g_prev[Nn * HIDD];
__device__ float g_q[Nn * HD];
__device__ float g_k[Nn * HD];
__device__ float g_v[Nn * HD];
__device__ float g_out[Nn * HD];
__device__ float g_rsq[Nn];
__device__ float g_kvs[2 * HIDD * HIDD];
__device__ float g_sumK[HD];
__device__ float g_sumV[HD];
__device__ float g_sums[2];
__device__ int   g_cnt[Nn];
__device__ int   g_ptr[Nn + 1];
__device__ int   g_cur[Nn];
__device__ int   g_erow[Ee];
__device__ int   g_blk[512];

// ---------------- tf32 mma helpers ----------------
__device__ __forceinline__ unsigned f2tf(float f) {
    unsigned u; asm("cvt.rna.tf32.f32 %0, %1;" : "=r"(u) : "f"(f)); return u;
}
__device__ __forceinline__ void tsplit(float f, unsigned& hi, unsigned& lo) {
    unsigned h = f2tf(f);
    float r = f - __uint_as_float(h);
    hi = h; lo = f2tf(r);
}
__device__ __forceinline__ void mma8(float* d, const unsigned* a, const unsigned* b) {
    asm volatile("mma.sync.aligned.m16n8k8.row.col.f32.tf32.tf32.f32 "
        "{%0,%1,%2,%3}, {%4,%5,%6,%7}, {%8,%9}, {%0,%1,%2,%3};"
        : "+f"(d[0]), "+f"(d[1]), "+f"(d[2]), "+f"(d[3])
        : "r"(a[0]), "r"(a[1]), "r"(a[2]), "r"(a[3]), "r"(b[0]), "r"(b[1]));
}

// ---------------- fc0: split-TF32 GEMM + bias + LN + ReLU ----------------
__global__ void k_fc0(const float* __restrict__ x, const float* __restrict__ w,
                      const float* __restrict__ bias, const float* __restrict__ lnw,
                      const float* __restrict__ lnb) {
    __shared__ float xs[64][68];   // [row][k]
    __shared__ float ws[64][68];   // [k][col]
    int tid = threadIdx.x, lane = tid & 31, warp = tid >> 5;
    int rw = warp & 3, cw = warp >> 2, g = lane >> 2, t = lane & 3;
    int row0 = blockIdx.x * 64;
    float acc[4][4] = {};
    for (int kc = 0; kc < 4; kc++) {
        __syncthreads();
#pragma unroll
        for (int l = 0; l < 4; l++) {
            int lin = tid + l * 256;
            int r = lin >> 4, c4 = lin & 15;
            int gr = row0 + r; if (gr >= Nn) gr = Nn - 1;
            *(float4*)&xs[r][c4 * 4] = *(const float4*)&x[(size_t)gr * INF + kc * 64 + c4 * 4];
            *(float4*)&ws[r][c4 * 4] = *(const float4*)&w[(size_t)(kc * 64 + r) * HIDD + c4 * 4];
        }
        __syncthreads();
#pragma unroll
        for (int ks = 0; ks < 8; ks++) {
            int k0 = ks * 8;
            unsigned ah[4], al[4];
#pragma unroll
            for (int i = 0; i < 4; i++) {
                int rr = rw * 16 + g + (i & 1) * 8;
                int kk = k0 + t + (i >> 1) * 4;
                tsplit(xs[rr][kk], ah[i], al[i]);
            }
#pragma unroll
            for (int nt = 0; nt < 4; nt++) {
                int c0 = cw * 32 + nt * 8;
                unsigned bh[2], bl[2];
                tsplit(ws[k0 + t][c0 + g], bh[0], bl[0]);
                tsplit(ws[k0 + t + 4][c0 + g], bh[1], bl[1]);
                mma8(acc[nt], ah, bh);
                mma8(acc[nt], ah, bl);
                mma8(acc[nt], al, bh);
            }
        }
    }
    __syncthreads();
#pragma unroll
    for (int nt = 0; nt < 4; nt++) {
        int c0 = cw * 32 + nt * 8 + t * 2;
        float b0v = bias[c0], b1v = bias[c0 + 1];
        int r0 = rw * 16 + g, r1 = r0 + 8;
        xs[r0][c0] = acc[nt][0] + b0v; xs[r0][c0 + 1] = acc[nt][1] + b1v;
        xs[r1][c0] = acc[nt][2] + b0v; xs[r1][c0 + 1] = acc[nt][3] + b1v;
    }
    __syncthreads();
    int r = tid >> 2, sub = tid & 3;
    float vbuf[16];
    float s = 0.f, sq = 0.f;
#pragma unroll
    for (int j = 0; j < 16; j++) { float v = xs[r][sub * 16 + j]; vbuf[j] = v; s += v; sq += v * v; }
    s += __shfl_xor_sync(FULL, s, 1); sq += __shfl_xor_sync(FULL, sq, 1);
    s += __shfl_xor_sync(FULL, s, 2); sq += __shfl_xor_sync(FULL, sq, 2);
    float mu = s * 0.015625f;
    float var = sq * 0.015625f - mu * mu;
    float rs = rsqrtf(var + EPSL);
    int gr = row0 + r;
    if (gr < Nn) {
#pragma unroll
        for (int j = 0; j < 16; j++) {
            int c = sub * 16 + j;
            float y = (vbuf[j] - mu) * rs * lnw[c] + lnb[c];
            y = fmaxf(y, 0.f);
            g_h[(size_t)gr * HIDD + c] = y;
            g_prev[(size_t)gr * HIDD + c] = y;
        }
    }
}

// ---------------- CSR build ----------------
__global__ void k_zcnt() { int i = blockIdx.x * 256 + threadIdx.x; if (i < Nn) g_cnt[i] = 0; }
__global__ void k_count(const int* __restrict__ col) {
    int e = blockIdx.x * 256 + threadIdx.x;
    if (e < Ee) atomicAdd(&g_cnt[col[e]], 1);
}
__global__ void k_rsqk() {
    int i = blockIdx.x * 256 + threadIdx.x;
    if (i < Nn) { int c = g_cnt[i]; g_rsq[i] = c > 0 ? rsqrtf((float)c) : 0.f; }
}
__device__ __forceinline__ int blockScanIncl(int val, int* wsum) {
    int lane = threadIdx.x & 31, wid = threadIdx.x >> 5;
#pragma unroll
    for (int o = 1; o < 32; o <<= 1) {
        int n = __shfl_up_sync(FULL, val, o);
        if (lane >= o) val += n;
    }
    if (lane == 31) wsum[wid] = val;
    __syncthreads();
    if (wid == 0) {
        int nw = blockDim.x >> 5;
        int w = (lane < nw) ? wsum[lane] : 0;
#pragma unroll
        for (int o = 1; o < 32; o <<= 1) {
            int n = __shfl_up_sync(FULL, w, o);
            if (lane >= o) w += n;
        }
        wsum[lane] = w;
    }
    __syncthreads();
    return val + (wid > 0 ? wsum[wid - 1] : 0);
}
__global__ void k_scan1() {
    __shared__ int wsum[32];
    int i = blockIdx.x * 256 + threadIdx.x;
    int v = (i < Nn) ? g_cnt[i] : 0;
    int incl = blockScanIncl(v, wsum);
    if (i < Nn) g_ptr[i] = incl - v;
    if (threadIdx.x == 255) g_blk[blockIdx.x] = incl;
}
__global__ void k_scan2() {
    __shared__ int wsum[32];
    const int NB = (Nn + 255) / 256;
    int v = (threadIdx.x < NB) ? g_blk[threadIdx.x] : 0;
    int incl = blockScanIncl(v, wsum);
    if (threadIdx.x < NB) g_blk[threadIdx.x] = incl - v;
}
__global__ void k_scan3() {
    int i = blockIdx.x * 256 + threadIdx.x;
    if (i < Nn) {
        int p = g_ptr[i] + g_blk[i >> 8];
        g_ptr[i] = p; g_cur[i] = p;
    }
    if (i == 0) g_ptr[Nn] = Ee;
}
__global__ void k_fill(const int* __restrict__ row, const int* __restrict__ col) {
    int e = blockIdx.x * 256 + threadIdx.x;
    if (e < Ee) {
        int c = col[e];
        int p = atomicAdd(&g_cur[c], 1);
        g_erow[p] = row[e];
    }
}

// ---------------- per-layer reduction zero ----------------
__global__ void k_zero_red() {
    int i = blockIdx.x * blockDim.x + threadIdx.x;
    int stride = gridDim.x * blockDim.x;
    for (int j = i; j < 8192; j += stride) g_kvs[j] = 0.f;
    if (i < HD) { g_sumK[i] = 0.f; g_sumV[i] = 0.f; }
    if (i < 2) g_sums[i] = 0.f;
}

// ---------------- QKV: split-TF32 GEMM + fused reductions ----------------
__global__ void k_qkv(const float* __restrict__ Wq, const float* __restrict__ Wk,
                      const float* __restrict__ Wv, const float* __restrict__ bq,
                      const float* __restrict__ bk, const float* __restrict__ bv) {
    __shared__ float hs[64][68];
    __shared__ float ws[64][68];
    __shared__ float sK[128], sV[128];
    int tid = threadIdx.x, lane = tid & 31, warp = tid >> 5;
    int rw = warp & 3, cw = warp >> 2, g = lane >> 2, t = lane & 3;
    int row0 = blockIdx.x * 64;
    if (tid < 128) { sK[tid] = 0.f; sV[tid] = 0.f; }
#pragma unroll
    for (int l = 0; l < 4; l++) {
        int lin = tid + l * 256;
        int r = lin >> 4, c4 = lin & 15;
        int gr = row0 + r;
        float4 v = make_float4(0.f, 0.f, 0.f, 0.f);
        if (gr < Nn) v = *(const float4*)&g_h[(size_t)gr * HIDD + c4 * 4];
        *(float4*)&hs[r][c4 * 4] = v;
    }
    float q2 = 0.f, k2 = 0.f;
    for (int ch = 0; ch < 6; ch++) {
        int mat = ch >> 1, cc2 = ch & 1;
        const float* W = mat == 0 ? Wq : (mat == 1 ? Wk : Wv);
        const float* B = mat == 0 ? bq : (mat == 1 ? bk : bv);
        float* dst = mat == 0 ? g_q : (mat == 1 ? g_k : g_v);
        __syncthreads();
#pragma unroll
        for (int l = 0; l < 4; l++) {
            int lin = tid + l * 256;
            int kk = lin >> 4, c4 = lin & 15;
            *(float4*)&ws[kk][c4 * 4] = *(const float4*)&W[(size_t)kk * HD + cc2 * 64 + c4 * 4];
        }
        __syncthreads();
        float acc[4][4] = {};
#pragma unroll
        for (int ks = 0; ks < 8; ks++) {
            int k0 = ks * 8;
            unsigned ah[4], al[4];
#pragma unroll
            for (int i = 0; i < 4; i++) {
                int rr = rw * 16 + g + (i & 1) * 8;
                int kk = k0 + t + (i >> 1) * 4;
                tsplit(hs[rr][kk], ah[i], al[i]);
            }
#pragma unroll
            for (int nt = 0; nt < 4; nt++) {
                int c0 = cw * 32 + nt * 8;
                unsigned bh[2], bl[2];
                tsplit(ws[k0 + t][c0 + g], bh[0], bl[0]);
                tsplit(ws[k0 + t + 4][c0 + g], bh[1], bl[1]);
                mma8(acc[nt], ah, bh);
                mma8(acc[nt], ah, bl);
                mma8(acc[nt], al, bh);
            }
        }
#pragma unroll
        for (int nt = 0; nt < 4; nt++) {
            int cgl = cc2 * 64 + cw * 32 + nt * 8 + t * 2;
            float b0v = B[cgl], b1v = B[cgl + 1];
            int r0 = row0 + rw * 16 + g, r1 = r0 + 8;
            float v00 = acc[nt][0] + b0v, v01 = acc[nt][1] + b1v;
            float v10 = acc[nt][2] + b0v, v11 = acc[nt][3] + b1v;
            if (r0 < Nn) *(float2*)&dst[(size_t)r0 * HD + cgl] = make_float2(v00, v01);
            else { v00 = 0.f; v01 = 0.f; }
            if (r1 < Nn) *(float2*)&dst[(size_t)r1 * HD + cgl] = make_float2(v10, v11);
            else { v10 = 0.f; v11 = 0.f; }
            if (mat == 0) {
                q2 += v00 * v00 + v01 * v01 + v10 * v10 + v11 * v11;
            } else {
                if (mat == 1) k2 += v00 * v00 + v01 * v01 + v10 * v10 + v11 * v11;
                float c0s = v00 + v10, c1s = v01 + v11;
                c0s += __shfl_xor_sync(FULL, c0s, 4);  c1s += __shfl_xor_sync(FULL, c1s, 4);
                c0s += __shfl_xor_sync(FULL, c0s, 8);  c1s += __shfl_xor_sync(FULL, c1s, 8);
                c0s += __shfl_xor_sync(FULL, c0s, 16); c1s += __shfl_xor_sync(FULL, c1s, 16);
                if (g == 0) {
                    float* sd = (mat == 1) ? sK : sV;
                    atomicAdd(&sd[cgl], c0s);
                    atomicAdd(&sd[cgl + 1], c1s);
                }
            }
        }
    }
#pragma unroll
    for (int o = 16; o > 0; o >>= 1) {
        q2 += __shfl_xor_sync(FULL, q2, o);
        k2 += __shfl_xor_sync(FULL, k2, o);
    }
    if (lane == 0) { atomicAdd(&g_sums[0], q2); atomicAdd(&g_sums[1], k2); }
    __syncthreads();
    if (tid < 128) { atomicAdd(&g_sumK[tid], sK[tid]); atomicAdd(&g_sumV[tid], sV[tid]); }
}

// ---------------- kvs = k^T v (TF32 mma) ----------------
__global__ void k_reduce() {
    __shared__ float ks[32][132];
    __shared__ float vs[32][132];
    int tid = threadIdx.x, lane = tid & 31, warp = tid >> 5;
    int h = warp >> 2, mw = warp & 3, g = lane >> 2, t = lane & 3;
    int hb = h * 64, m0 = mw * 16;
    float acc[8][4] = {};
    int ntiles = (Nn + 31) / 32;
    for (int tt = blockIdx.x; tt < ntiles; tt += gridDim.x) {
        __syncthreads();
#pragma unroll
        for (int l = 0; l < 4; l++) {
            int lin = tid + l * 256;
            int nl = lin >> 5, c4 = lin & 31;
            int n = tt * 32 + nl;
            float4 kv = make_float4(0.f, 0.f, 0.f, 0.f), vv = kv;
            if (n < Nn) {
                kv = *(const float4*)&g_k[(size_t)n * HD + c4 * 4];
                vv = *(const float4*)&g_v[(size_t)n * HD + c4 * 4];
            }
            *(float4*)&ks[nl][c4 * 4] = kv;
            *(float4*)&vs[nl][c4 * 4] = vv;
        }
        __syncthreads();
#pragma unroll
        for (int ksr = 0; ksr < 4; ksr++) {
            int k0 = ksr * 8;
            unsigned a[4];
            a[0] = f2tf(ks[k0 + t][hb + m0 + g]);
            a[1] = f2tf(ks[k0 + t][hb + m0 + g + 8]);
            a[2] = f2tf(ks[k0 + t + 4][hb + m0 + g]);
            a[3] = f2tf(ks[k0 + t + 4][hb + m0 + g + 8]);
#pragma unroll
            for (int nt = 0; nt < 8; nt++) {
                int d0 = nt * 8;
                unsigned b[2];
                b[0] = f2tf(vs[k0 + t][hb + d0 + g]);
                b[1] = f2tf(vs[k0 + t + 4][hb + d0 + g]);
                mma8(acc[nt], a, b);
            }
        }
    }
#pragma unroll
    for (int nt = 0; nt < 8; nt++) {
        int c0 = nt * 8 + t * 2;
        int r0 = m0 + g, r1 = r0 + 8;
        atomicAdd(&g_kvs[h * 4096 + r0 * 64 + c0],     acc[nt][0]);
        atomicAdd(&g_kvs[h * 4096 + r0 * 64 + c0 + 1], acc[nt][1]);
        atomicAdd(&g_kvs[h * 4096 + r1 * 64 + c0],     acc[nt][2]);
        atomicAdd(&g_kvs[h * 4096 + r1 * 64 + c0 + 1], acc[nt][3]);
    }
}

// ---------------- attention output (TF32 mma) ----------------
__global__ void k_attn() {
    __shared__ float qs[64][68];
    __shared__ float kvt[64][68];
    __shared__ float sKs[64], sVs[64], den[64];
    int tid = threadIdx.x, lane = tid & 31, warp = tid >> 5;
    int rw = warp & 3, cw = warp >> 2, g = lane >> 2, t = lane & 3;
    int row0 = blockIdx.x * 64;
    float sc = rsqrtf(g_sums[0] * g_sums[1]);
    for (int h = 0; h < 2; h++) {
        __syncthreads();
#pragma unroll
        for (int l = 0; l < 4; l++) {
            int lin = tid + l * 256;
            int r = lin >> 4, c4 = lin & 15;
            *(float4*)&kvt[r][c4 * 4] = *(const float4*)&g_kvs[h * 4096 + r * 64 + c4 * 4];
            int gr = row0 + r;
            float4 qv = make_float4(0.f, 0.f, 0.f, 0.f);
            if (gr < Nn) qv = *(const float4*)&g_q[(size_t)gr * HD + h * 64 + c4 * 4];
            *(float4*)&qs[r][c4 * 4] = qv;
        }
        if (tid < 64) { sKs[tid] = g_sumK[h * 64 + tid]; sVs[tid] = g_sumV[h * 64 + tid]; }
        __syncthreads();
        float acc[4][4] = {};
#pragma unroll
        for (int ksr = 0; ksr < 8; ksr++) {
            int k0 = ksr * 8;
            unsigned a[4];
            a[0] = f2tf(qs[rw * 16 + g][k0 + t]);
            a[1] = f2tf(qs[rw * 16 + g + 8][k0 + t]);
            a[2] = f2tf(qs[rw * 16 + g][k0 + t + 4]);
            a[3] = f2tf(qs[rw * 16 + g + 8][k0 + t + 4]);
#pragma unroll
            for (int nt = 0; nt < 4; nt++) {
                int c0 = cw * 32 + nt * 8;
                unsigned b[2];
                b[0] = f2tf(kvt[k0 + t][c0 + g]);
                b[1] = f2tf(kvt[k0 + t + 4][c0 + g]);
                mma8(acc[nt], a, b);
            }
        }
        if (tid < 64) {
            float a = 0.f;
#pragma unroll
            for (int m = 0; m < 64; m++) a += qs[tid][m] * sKs[m];
            den[tid] = a * sc + (float)Nn;
        }
        __syncthreads();
#pragma unroll
        for (int nt = 0; nt < 4; nt++) {
            int c0 = cw * 32 + nt * 8 + t * 2;
            int r0 = rw * 16 + g, r1 = r0 + 8;
            if (row0 + r0 < Nn) {
                float dn = den[r0];
                float n0 = acc[nt][0] * sc + sVs[c0], n1 = acc[nt][1] * sc + sVs[c0 + 1];
                *(float2*)&g_out[(size_t)(row0 + r0) * HD + h * 64 + c0] = make_float2(n0 / dn, n1 / dn);
            }
            if (row0 + r1 < Nn) {
                float dn = den[r1];
                float n0 = acc[nt][2] * sc + sVs[c0], n1 = acc[nt][3] * sc + sVs[c0 + 1];
                *(float2*)&g_out[(size_t)(row0 + r1) * HD + h * 64 + c0] = make_float2(n0 / dn, n1 / dn);
            }
        }
    }
}

// ---------------- fused GCN gather + head-mean + residual + LN ----------------
__global__ void k_gcnc(const float* __restrict__ lnw, const float* __restrict__ lnb) {
    int lane = threadIdx.x & 31;
    int n = blockIdx.x * 8 + (threadIdx.x >> 5);
    if (n >= Nn) return;
    int p0 = g_ptr[n], p1 = g_ptr[n + 1];
    float rn = g_rsq[n];
    float4 acc = make_float4(0.f, 0.f, 0.f, 0.f);
    for (int e = p0; e < p1; e++) {
        int r = g_erow[e];
        float w = rn * g_rsq[r];
        float4 v = *(const float4*)&g_v[(size_t)r * HD + lane * 4];
        acc.x += w * v.x; acc.y += w * v.y; acc.z += w * v.z; acc.w += w * v.w;
    }
    float4 o = *(const float4*)&g_out[(size_t)n * HD + lane * 4];
    o.x += acc.x; o.y += acc.y; o.z += acc.z; o.w += acc.w;
    float4 m4;
    m4.x = 0.5f * (o.x + __shfl_xor_sync(FULL, o.x, 16));
    m4.y = 0.5f * (o.y + __shfl_xor_sync(FULL, o.y, 16));
    m4.z = 0.5f * (o.z + __shfl_xor_sync(FULL, o.z, 16));
    m4.w = 0.5f * (o.w + __shfl_xor_sync(FULL, o.w, 16));
    if (lane < 16) {
        float4 pv = *(const float4*)&g_prev[(size_t)n * HIDD + lane * 4];
        float4 hv;
        hv.x = 0.5f * m4.x + 0.5f * pv.x;
        hv.y = 0.5f * m4.y + 0.5f * pv.y;
        hv.z = 0.5f * m4.z + 0.5f * pv.z;
        hv.w = 0.5f * m4.w + 0.5f * pv.w;
        float s = hv.x + hv.y + hv.z + hv.w;
        float sq = hv.x * hv.x + hv.y * hv.y + hv.z * hv.z + hv.w * hv.w;
#pragma unroll
        for (int o2 = 1; o2 < 16; o2 <<= 1) {
            s += __shfl_xor_sync(0x0000ffffu, s, o2);
            sq += __shfl_xor_sync(0x0000ffffu, sq, o2);
        }
        float mu = s * 0.015625f;
        float var = sq * 0.015625f - mu * mu;
        float rs = rsqrtf(var + EPSL);
        float4 lw = *(const float4*)&lnw[lane * 4];
        float4 lb = *(const float4*)&lnb[lane * 4];
        float4 y;
        y.x = (hv.x - mu) * rs * lw.x + lb.x;
        y.y = (hv.y - mu) * rs * lw.y + lb.y;
        y.z = (hv.z - mu) * rs * lw.z + lb.z;
        y.w = (hv.w - mu) * rs * lw.w + lb.w;
        *(float4*)&g_h[(size_t)n * HIDD + lane * 4] = y;
        *(float4*)&g_prev[(size_t)n * HIDD + lane * 4] = y;
    }
}

// ---------------- final projection ----------------
__global__ void k_fco(const float* __restrict__ w, const float* __restrict__ b,
                      float* __restrict__ out) {
    __shared__ float ws[64][40];
    __shared__ float hs[64][65];
    int tid = threadIdx.x;
    int row0 = blockIdx.x * 64;
    for (int l = tid; l < 64 * 40; l += 256) ws[l / 40][l % 40] = w[l];
#pragma unroll
    for (int l = 0; l < 4; l++) {
        int lin = tid + l * 256;
        int r = lin >> 4, c4 = lin & 15;
        int gr = row0 + r; if (gr >= Nn) gr = Nn - 1;
        float4 v = *(const float4*)&g_h[(size_t)gr * HIDD + c4 * 4];
        hs[r][c4 * 4 + 0] = v.x; hs[r][c4 * 4 + 1] = v.y;
        hs[r][c4 * 4 + 2] = v.z; hs[r][c4 * 4 + 3] = v.w;
    }
    __syncthreads();
    int r = tid & 63, cg = tid >> 6;
    float acc[10] = {};
#pragma unroll
    for (int kk = 0; kk < 64; kk++) {
        float a = hs[r][kk];
        const float* wr = &ws[kk][cg * 10];
#pragma unroll
        for (int j = 0; j < 10; j++) acc[j] += a * wr[j];
    }
    int gr = row0 + r;
    if (gr < Nn) {
#pragma unroll
        for (int j = 0; j < 10; j++)
            out[(size_t)gr * CC + cg * 10 + j] = acc[j] + b[cg * 10 + j];
    }
}

// ---------------- launcher ----------------
extern "C" void kernel_launch(void* const* d_in, const int* in_sizes, int n_in,
                              void* d_out, int out_size) {
    (void)in_sizes; (void)n_in; (void)out_size;
    const float* x     = (const float*)d_in[0];
    const int*   ei    = (const int*)d_in[1];
    const float* fc0_w = (const float*)d_in[2];
    const float* fc0_b = (const float*)d_in[3];
    const float* ln_w  = (const float*)d_in[4];
    const float* ln_b  = (const float*)d_in[5];
    const float* Wq    = (const float*)d_in[6];
    const float* Wk    = (const float*)d_in[7];
    const float* Wv    = (const float*)d_in[8];
    const float* bq    = (const float*)d_in[9];
    const float* bk    = (const float*)d_in[10];
    const float* bv    = (const float*)d_in[11];
    const float* fco_w = (const float*)d_in[12];
    const float* fco_b = (const float*)d_in[13];
    float* out = (float*)d_out;

    const int GB = (Nn + 63) / 64;      // 1563
    const int NB = (Nn + 255) / 256;    // 391
    const int EB = (Ee + 255) / 256;    // 3125

    k_fc0<<<GB, 256>>>(x, fc0_w, fc0_b, ln_w, ln_b);
    k_zcnt<<<NB, 256>>>();
    k_count<<<EB, 256>>>(ei + Ee);
    k_rsqk<<<NB, 256>>>();
    k_scan1<<<NB, 256>>>();
    k_scan2<<<1, 512>>>();
    k_scan3<<<NB, 256>>>();
    k_fill<<<EB, 256>>>(ei, ei + Ee);

    for (int l = 0; l < 2; l++) {
        k_zero_red<<<34, 256>>>();
        k_qkv<<<GB, 256>>>(Wq + (size_t)l * HIDD * HD, Wk + (size_t)l * HIDD * HD,
                           Wv + (size_t)l * HIDD * HD,
                           bq + l * HD, bk + l * HD, bv + l * HD);
        k_reduce<<<128, 256>>>();
        k_attn<<<GB, 256>>>();
        k_gcnc<<<(Nn + 7) / 8, 256>>>(ln_w + (l + 1) * HIDD, ln_b + (l + 1) * HIDD);
    }
    k_fco<<<GB, 256>>>(fco_w, fco_b, out);
}

// round 4
// speedup vs baseline: 1.1557x; 1.0967x over previous
#include <cuda_runtime.h>

#define Nn    100000
#define Ee    800000
#define INF   256
#define HIDD  64
#define HD    128
#define CC    40
#define EPSL  1e-5f
#define FULL  0xffffffffu

// ---------------- scratch ----------------
__device__ float g_h[Nn * HIDD];
__device__ float g_prev[Nn * HIDD];
__device__ float g_q[Nn * HD];
__device__ float g_k[Nn * HD];
__device__ float g_v[Nn * HD];
__device__ float g_out[Nn * HD];
__device__ float g_rsq[Nn];
__device__ float g_kvs[2 * HIDD * HIDD];
__device__ float g_sumK[HD];
__device__ float g_sumV[HD];
__device__ float g_sums[2];
__device__ int   g_cnt[Nn];
__device__ int   g_ptr[Nn + 1];
__device__ int   g_cur[Nn];
__device__ int   g_erow[Ee];
__device__ int   g_blk[512];
// split-bf16 activation h (pair-packed along k): [n][32] uint (bf16x2)
__device__ unsigned g_hh[Nn * 32];
__device__ unsigned g_hl[Nn * 32];
// pre-split weights in fragment order (2048 uints per 64x64 chunk)
__device__ unsigned g_w0h[8192], g_w0l[8192];       // fc0_w: [kc4][2048]
__device__ unsigned g_wfh[24576], g_wfl[24576];     // qkv: [L2][mat3][cc2][2048]

// ---------------- bf16 helpers ----------------
__device__ __forceinline__ unsigned packbf2(float f0, float f1) {
    unsigned r; asm("cvt.rn.bf16x2.f32 %0, %1, %2;" : "=r"(r) : "f"(f1), "f"(f0)); return r;
}
__device__ __forceinline__ void bsplit2(float f0, float f1, unsigned& h, unsigned& l) {
    h = packbf2(f0, f1);
    float h0 = __uint_as_float(h << 16);
    float h1 = __uint_as_float(h & 0xffff0000u);
    l = packbf2(f0 - h0, f1 - h1);
}
__device__ __forceinline__ void mma16(float* d, const unsigned* a, const unsigned* b) {
    asm volatile("mma.sync.aligned.m16n8k16.row.col.f32.bf16.bf16.f32 "
        "{%0,%1,%2,%3}, {%4,%5,%6,%7}, {%8,%9}, {%0,%1,%2,%3};"
        : "+f"(d[0]), "+f"(d[1]), "+f"(d[2]), "+f"(d[3])
        : "r"(a[0]), "r"(a[1]), "r"(a[2]), "r"(a[3]), "r"(b[0]), "r"(b[1]));
}
// tf32 helpers (reduce/attn)
__device__ __forceinline__ unsigned f2tf(float f) {
    unsigned u; asm("cvt.rna.tf32.f32 %0, %1;" : "=r"(u) : "f"(f)); return u;
}
__device__ __forceinline__ void mma8(float* d, const unsigned* a, const unsigned* b) {
    asm volatile("mma.sync.aligned.m16n8k8.row.col.f32.tf32.tf32.f32 "
        "{%0,%1,%2,%3}, {%4,%5,%6,%7}, {%8,%9}, {%0,%1,%2,%3};"
        : "+f"(d[0]), "+f"(d[1]), "+f"(d[2]), "+f"(d[3])
        : "r"(a[0]), "r"(a[1]), "r"(a[2]), "r"(a[3]), "r"(b[0]), "r"(b[1]));
}

// ---------------- weight pre-split (fragment order) ----------------
// B chunk layout (per 64k x 64n): index = ((kt*8 + ntg)*32 + lane)*2 + reg
//   element (k, c): kt=k>>4, reg=(k>>3)&1, t=(k&7)>>1 (pair), ntg=c>>3, g=c&7
__global__ void k_prep(const float* __restrict__ fc0_w, const float* __restrict__ Wq,
                       const float* __restrict__ Wk, const float* __restrict__ Wv) {
    int id = blockIdx.x * 256 + threadIdx.x;   // 32768 total
    if (id < 8192) {
        int kc = id >> 11, rem = id & 2047;
        int reg = rem & 1, lane = (rem >> 1) & 31, ntg = (rem >> 6) & 7, kt = rem >> 9;
        int t = lane & 3, gg = lane >> 2;
        int k = kc * 64 + kt * 16 + reg * 8 + 2 * t;
        int c = ntg * 8 + gg;
        float f0 = fc0_w[k * HIDD + c], f1 = fc0_w[(k + 1) * HIDD + c];
        unsigned h, l; bsplit2(f0, f1, h, l);
        g_w0h[id] = h; g_w0l[id] = l;
    } else if (id < 32768) {
        int id2 = id - 8192;                  // 0..24575
        int layer = id2 / 12288, r3 = id2 % 12288;
        int mat = r3 >> 12, cc2 = (r3 >> 11) & 1, rem = r3 & 2047;
        int reg = rem & 1, lane = (rem >> 1) & 31, ntg = (rem >> 6) & 7, kt = rem >> 9;
        int t = lane & 3, gg = lane >> 2;
        const float* W = (mat == 0 ? Wq : (mat == 1 ? Wk : Wv)) + (size_t)layer * HIDD * HD;
        int k = kt * 16 + reg * 8 + 2 * t;
        int cg = cc2 * 64 + ntg * 8 + gg;
        float f0 = W[k * HD + cg], f1 = W[(k + 1) * HD + cg];
        unsigned h, l; bsplit2(f0, f1, h, l);
        g_wfh[id2] = h; g_wfl[id2] = l;
    }
}

// frag position for A element pair: row r (0..63), pair p (0..31)
__device__ __forceinline__ int aFragPos(int r, int p) {
    return (((r >> 4) * 4 + (p >> 3)) * 32 + ((r & 7) * 4 + (p & 3))) * 4
           + ((r >> 3) & 1) + 2 * ((p >> 2) & 1);
}

// ---------------- fc0: split-bf16 GEMM + bias + LN + ReLU ----------------
__global__ void k_fc0(const float* __restrict__ x, const float* __restrict__ bias,
                      const float* __restrict__ lnw, const float* __restrict__ lnb) {
    __shared__ __align__(16) unsigned sm[8192];   // AH 2048 | AL 2048 | BH 2048 | BL 2048
    float* scr = (float*)sm;
    int tid = threadIdx.x, lane = tid & 31, warp = tid >> 5;
    int rw = warp & 3, cw = warp >> 2, g = lane >> 2, t = lane & 3;
    int row0 = blockIdx.x * 64;
    float acc[4][4] = {};
    for (int kc = 0; kc < 4; kc++) {
        __syncthreads();
#pragma unroll
        for (int i = 0; i < 8; i++) {
            int idx = tid + i * 256;
            sm[4096 + idx] = g_w0h[kc * 2048 + idx];
            sm[6144 + idx] = g_w0l[kc * 2048 + idx];
        }
#pragma unroll
        for (int i = 0; i < 4; i++) {
            int idx = tid + i * 256;
            int r = idx >> 4, q4 = idx & 15;
            int gr = row0 + r;
            float4 v = make_float4(0.f, 0.f, 0.f, 0.f);
            if (gr < Nn) v = *(const float4*)&x[(size_t)gr * INF + kc * 64 + q4 * 4];
            unsigned h0, l0, h1, l1;
            bsplit2(v.x, v.y, h0, l0);
            bsplit2(v.z, v.w, h1, l1);
            int pos0 = aFragPos(r, q4 * 2);
            int pos1 = aFragPos(r, q4 * 2 + 1);
            sm[pos0] = h0; sm[2048 + pos0] = l0;
            sm[pos1] = h1; sm[2048 + pos1] = l1;
        }
        __syncthreads();
#pragma unroll
        for (int kt = 0; kt < 4; kt++) {
            uint4 ah = *(uint4*)&sm[((rw * 4 + kt) * 32 + lane) * 4];
            uint4 al = *(uint4*)&sm[2048 + ((rw * 4 + kt) * 32 + lane) * 4];
#pragma unroll
            for (int nt = 0; nt < 4; nt++) {
                int ntg = cw * 4 + nt;
                uint2 bh = *(uint2*)&sm[4096 + ((kt * 8 + ntg) * 32 + lane) * 2];
                uint2 bl = *(uint2*)&sm[6144 + ((kt * 8 + ntg) * 32 + lane) * 2];
                mma16(acc[nt], (const unsigned*)&ah, (const unsigned*)&bh);
                mma16(acc[nt], (const unsigned*)&ah, (const unsigned*)&bl);
                mma16(acc[nt], (const unsigned*)&al, (const unsigned*)&bh);
            }
        }
    }
    __syncthreads();
#pragma unroll
    for (int nt = 0; nt < 4; nt++) {
        int c0 = cw * 32 + nt * 8 + t * 2;
        float b0v = bias[c0], b1v = bias[c0 + 1];
        int r0 = rw * 16 + g, r1 = r0 + 8;
        scr[r0 * 68 + c0] = acc[nt][0] + b0v; scr[r0 * 68 + c0 + 1] = acc[nt][1] + b1v;
        scr[r1 * 68 + c0] = acc[nt][2] + b0v; scr[r1 * 68 + c0 + 1] = acc[nt][3] + b1v;
    }
    __syncthreads();
    int r = tid >> 2, sub = tid & 3;
    float vbuf[16];
    float s = 0.f, sq = 0.f;
#pragma unroll
    for (int j = 0; j < 16; j++) { float v = scr[r * 68 + sub * 16 + j]; vbuf[j] = v; s += v; sq += v * v; }
    s += __shfl_xor_sync(FULL, s, 1); sq += __shfl_xor_sync(FULL, sq, 1);
    s += __shfl_xor_sync(FULL, s, 2); sq += __shfl_xor_sync(FULL, sq, 2);
    float mu = s * 0.015625f;
    float var = sq * 0.015625f - mu * mu;
    float rs = rsqrtf(var + EPSL);
    int gr = row0 + r;
    if (gr < Nn) {
        float y[16];
#pragma unroll
        for (int j = 0; j < 16; j++) {
            int c = sub * 16 + j;
            float yy = (vbuf[j] - mu) * rs * lnw[c] + lnb[c];
            yy = fmaxf(yy, 0.f);
            y[j] = yy;
            g_prev[(size_t)gr * HIDD + c] = yy;
        }
#pragma unroll
        for (int jp = 0; jp < 8; jp++) {
            unsigned h, l; bsplit2(y[2 * jp], y[2 * jp + 1], h, l);
            g_hh[(size_t)gr * 32 + sub * 8 + jp] = h;
            g_hl[(size_t)gr * 32 + sub * 8 + jp] = l;
        }
    }
}

// ---------------- CSR build ----------------
__global__ void k_zcnt() { int i = blockIdx.x * 256 + threadIdx.x; if (i < Nn) g_cnt[i] = 0; }
__global__ void k_count(const int* __restrict__ col) {
    int e = blockIdx.x * 256 + threadIdx.x;
    if (e < Ee) atomicAdd(&g_cnt[col[e]], 1);
}
__global__ void k_rsqk() {
    int i = blockIdx.x * 256 + threadIdx.x;
    if (i < Nn) { int c = g_cnt[i]; g_rsq[i] = c > 0 ? rsqrtf((float)c) : 0.f; }
}
__device__ __forceinline__ int blockScanIncl(int val, int* wsum) {
    int lane = threadIdx.x & 31, wid = threadIdx.x >> 5;
#pragma unroll
    for (int o = 1; o < 32; o <<= 1) {
        int n = __shfl_up_sync(FULL, val, o);
        if (lane >= o) val += n;
    }
    if (lane == 31) wsum[wid] = val;
    __syncthreads();
    if (wid == 0) {
        int nw = blockDim.x >> 5;
        int w = (lane < nw) ? wsum[lane] : 0;
#pragma unroll
        for (int o = 1; o < 32; o <<= 1) {
            int n = __shfl_up_sync(FULL, w, o);
            if (lane >= o) w += n;
        }
        wsum[lane] = w;
    }
    __syncthreads();
    return val + (wid > 0 ? wsum[wid - 1] : 0);
}
__global__ void k_scan1() {
    __shared__ int wsum[32];
    int i = blockIdx.x * 256 + threadIdx.x;
    int v = (i < Nn) ? g_cnt[i] : 0;
    int incl = blockScanIncl(v, wsum);
    if (i < Nn) g_ptr[i] = incl - v;
    if (threadIdx.x == 255) g_blk[blockIdx.x] = incl;
}
__global__ void k_scan2() {
    __shared__ int wsum[32];
    const int NB = (Nn + 255) / 256;
    int v = (threadIdx.x < NB) ? g_blk[threadIdx.x] : 0;
    int incl = blockScanIncl(v, wsum);
    if (threadIdx.x < NB) g_blk[threadIdx.x] = incl - v;
}
__global__ void k_scan3() {
    int i = blockIdx.x * 256 + threadIdx.x;
    if (i < Nn) {
        int p = g_ptr[i] + g_blk[i >> 8];
        g_ptr[i] = p; g_cur[i] = p;
    }
    if (i == 0) g_ptr[Nn] = Ee;
}
__global__ void k_fill(const int* __restrict__ row, const int* __restrict__ col) {
    int e = blockIdx.x * 256 + threadIdx.x;
    if (e < Ee) {
        int c = col[e];
        int p = atomicAdd(&g_cur[c], 1);
        g_erow[p] = row[e];
    }
}

// ---------------- per-layer reduction zero ----------------
__global__ void k_zero_red() {
    int i = blockIdx.x * blockDim.x + threadIdx.x;
    int stride = gridDim.x * blockDim.x;
    for (int j = i; j < 8192; j += stride) g_kvs[j] = 0.f;
    if (i < HD) { g_sumK[i] = 0.f; g_sumV[i] = 0.f; }
    if (i < 2) g_sums[i] = 0.f;
}

// ---------------- QKV: pre-split bf16 frag GEMM + fused reductions ----------------
__global__ void k_qkv(int layer, const float* __restrict__ bq,
                      const float* __restrict__ bk, const float* __restrict__ bv) {
    __shared__ __align__(16) unsigned sm[8192];
    __shared__ float sK[128], sV[128];
    int tid = threadIdx.x, lane = tid & 31, warp = tid >> 5;
    int rw = warp & 3, cw = warp >> 2, g = lane >> 2, t = lane & 3;
    int row0 = blockIdx.x * 64;
    const unsigned* wfh = g_wfh + layer * 12288;
    const unsigned* wfl = g_wfl + layer * 12288;
    if (tid < 128) { sK[tid] = 0.f; sV[tid] = 0.f; }
#pragma unroll
    for (int i = 0; i < 8; i++) {
        int idx = tid + i * 256;
        int r = idx >> 5, p = idx & 31;
        int gr = row0 + r;
        unsigned hv = 0, lv = 0;
        if (gr < Nn) { hv = g_hh[(size_t)gr * 32 + p]; lv = g_hl[(size_t)gr * 32 + p]; }
        int pos = aFragPos(r, p);
        sm[pos] = hv; sm[2048 + pos] = lv;
    }
    float q2 = 0.f, k2 = 0.f;
    for (int ch = 0; ch < 6; ch++) {
        int mat = ch >> 1, cc2 = ch & 1;
        const float* B = mat == 0 ? bq : (mat == 1 ? bk : bv);
        float* dst = mat == 0 ? g_q : (mat == 1 ? g_k : g_v);
        bool split = (mat == 2);
        __syncthreads();
#pragma unroll
        for (int i = 0; i < 8; i++) {
            int idx = tid + i * 256;
            sm[4096 + idx] = wfh[ch * 2048 + idx];
            sm[6144 + idx] = wfl[ch * 2048 + idx];
        }
        __syncthreads();
        float acc[4][4] = {};
#pragma unroll
        for (int kt = 0; kt < 4; kt++) {
            uint4 ah = *(uint4*)&sm[((rw * 4 + kt) * 32 + lane) * 4];
            uint4 al;
            if (split) al = *(uint4*)&sm[2048 + ((rw * 4 + kt) * 32 + lane) * 4];
#pragma unroll
            for (int nt = 0; nt < 4; nt++) {
                int ntg = cw * 4 + nt;
                uint2 bh = *(uint2*)&sm[4096 + ((kt * 8 + ntg) * 32 + lane) * 2];
                mma16(acc[nt], (const unsigned*)&ah, (const unsigned*)&bh);
                if (split) {
                    uint2 bl = *(uint2*)&sm[6144 + ((kt * 8 + ntg) * 32 + lane) * 2];
                    mma16(acc[nt], (const unsigned*)&ah, (const unsigned*)&bl);
                    mma16(acc[nt], (const unsigned*)&al, (const unsigned*)&bh);
                }
            }
        }
#pragma unroll
        for (int nt = 0; nt < 4; nt++) {
            int cgl = cc2 * 64 + cw * 32 + nt * 8 + t * 2;
            float b0v = B[cgl], b1v = B[cgl + 1];
            int r0 = row0 + rw * 16 + g, r1 = r0 + 8;
            float v00 = acc[nt][0] + b0v, v01 = acc[nt][1] + b1v;
            float v10 = acc[nt][2] + b0v, v11 = acc[nt][3] + b1v;
            if (r0 < Nn) *(float2*)&dst[(size_t)r0 * HD + cgl] = make_float2(v00, v01);
            else { v00 = 0.f; v01 = 0.f; }
            if (r1 < Nn) *(float2*)&dst[(size_t)r1 * HD + cgl] = make_float2(v10, v11);
            else { v10 = 0.f; v11 = 0.f; }
            if (mat == 0) {
                q2 += v00 * v00 + v01 * v01 + v10 * v10 + v11 * v11;
            } else {
                if (mat == 1) k2 += v00 * v00 + v01 * v01 + v10 * v10 + v11 * v11;
                float c0s = v00 + v10, c1s = v01 + v11;
                c0s += __shfl_xor_sync(FULL, c0s, 4);  c1s += __shfl_xor_sync(FULL, c1s, 4);
                c0s += __shfl_xor_sync(FULL, c0s, 8);  c1s += __shfl_xor_sync(FULL, c1s, 8);
                c0s += __shfl_xor_sync(FULL, c0s, 16); c1s += __shfl_xor_sync(FULL, c1s, 16);
                if (g == 0) {
                    float* sd = (mat == 1) ? sK : sV;
                    atomicAdd(&sd[cgl], c0s);
                    atomicAdd(&sd[cgl + 1], c1s);
                }
            }
        }
    }
#pragma unroll
    for (int o = 16; o > 0; o >>= 1) {
        q2 += __shfl_xor_sync(FULL, q2, o);
        k2 += __shfl_xor_sync(FULL, k2, o);
    }
    if (lane == 0) { atomicAdd(&g_sums[0], q2); atomicAdd(&g_sums[1], k2); }
    __syncthreads();
    if (tid < 128) { atomicAdd(&g_sumK[tid], sK[tid]); atomicAdd(&g_sumV[tid], sV[tid]); }
}

// ---------------- kvs = k^T v (TF32 mma) ----------------
__global__ void k_reduce() {
    __shared__ float ks[32][132];
    __shared__ float vs[32][132];
    int tid = threadIdx.x, lane = tid & 31, warp = tid >> 5;
    int h = warp >> 2, mw = warp & 3, g = lane >> 2, t = lane & 3;
    int hb = h * 64, m0 = mw * 16;
    float acc[8][4] = {};
    int ntiles = (Nn + 31) / 32;
    for (int tt = blockIdx.x; tt < ntiles; tt += gridDim.x) {
        __syncthreads();
#pragma unroll
        for (int l = 0; l < 4; l++) {
            int lin = tid + l * 256;
            int nl = lin >> 5, c4 = lin & 31;
            int n = tt * 32 + nl;
            float4 kv = make_float4(0.f, 0.f, 0.f, 0.f), vv = kv;
            if (n < Nn) {
                kv = *(const float4*)&g_k[(size_t)n * HD + c4 * 4];
                vv = *(const float4*)&g_v[(size_t)n * HD + c4 * 4];
            }
            *(float4*)&ks[nl][c4 * 4] = kv;
            *(float4*)&vs[nl][c4 * 4] = vv;
        }
        __syncthreads();
#pragma unroll
        for (int ksr = 0; ksr < 4; ksr++) {
            int k0 = ksr * 8;
            unsigned a[4];
            a[0] = f2tf(ks[k0 + t][hb + m0 + g]);
            a[1] = f2tf(ks[k0 + t][hb + m0 + g + 8]);
            a[2] = f2tf(ks[k0 + t + 4][hb + m0 + g]);
            a[3] = f2tf(ks[k0 + t + 4][hb + m0 + g + 8]);
#pragma unroll
            for (int nt = 0; nt < 8; nt++) {
                int d0 = nt * 8;
                unsigned b[2];
                b[0] = f2tf(vs[k0 + t][hb + d0 + g]);
                b[1] = f2tf(vs[k0 + t + 4][hb + d0 + g]);
                mma8(acc[nt], a, b);
            }
        }
    }
#pragma unroll
    for (int nt = 0; nt < 8; nt++) {
        int c0 = nt * 8 + t * 2;
        int r0 = m0 + g, r1 = r0 + 8;
        atomicAdd(&g_kvs[h * 4096 + r0 * 64 + c0],     acc[nt][0]);
        atomicAdd(&g_kvs[h * 4096 + r0 * 64 + c0 + 1], acc[nt][1]);
        atomicAdd(&g_kvs[h * 4096 + r1 * 64 + c0],     acc[nt][2]);
        atomicAdd(&g_kvs[h * 4096 + r1 * 64 + c0 + 1], acc[nt][3]);
    }
}

// ---------------- attention output (TF32 mma) ----------------
__global__ void k_attn() {
    __shared__ float qs[64][68];
    __shared__ float kvt[64][68];
    __shared__ float sKs[64], sVs[64], den[64];
    int tid = threadIdx.x, lane = tid & 31, warp = tid >> 5;
    int rw = warp & 3, cw = warp >> 2, g = lane >> 2, t = lane & 3;
    int row0 = blockIdx.x * 64;
    float sc = rsqrtf(g_sums[0] * g_sums[1]);
    for (int h = 0; h < 2; h++) {
        __syncthreads();
#pragma unroll
        for (int l = 0; l < 4; l++) {
            int lin = tid + l * 256;
            int r = lin >> 4, c4 = lin & 15;
            *(float4*)&kvt[r][c4 * 4] = *(const float4*)&g_kvs[h * 4096 + r * 64 + c4 * 4];
            int gr = row0 + r;
            float4 qv = make_float4(0.f, 0.f, 0.f, 0.f);
            if (gr < Nn) qv = *(const float4*)&g_q[(size_t)gr * HD + h * 64 + c4 * 4];
            *(float4*)&qs[r][c4 * 4] = qv;
        }
        if (tid < 64) { sKs[tid] = g_sumK[h * 64 + tid]; sVs[tid] = g_sumV[h * 64 + tid]; }
        __syncthreads();
        float acc[4][4] = {};
#pragma unroll
        for (int ksr = 0; ksr < 8; ksr++) {
            int k0 = ksr * 8;
            unsigned a[4];
            a[0] = f2tf(qs[rw * 16 + g][k0 + t]);
            a[1] = f2tf(qs[rw * 16 + g + 8][k0 + t]);
            a[2] = f2tf(qs[rw * 16 + g][k0 + t + 4]);
            a[3] = f2tf(qs[rw * 16 + g + 8][k0 + t + 4]);
#pragma unroll
            for (int nt = 0; nt < 4; nt++) {
                int c0 = cw * 32 + nt * 8;
                unsigned b[2];
                b[0] = f2tf(kvt[k0 + t][c0 + g]);
                b[1] = f2tf(kvt[k0 + t + 4][c0 + g]);
                mma8(acc[nt], a, b);
            }
        }
        if (tid < 64) {
            float a = 0.f;
#pragma unroll
            for (int m = 0; m < 64; m++) a += qs[tid][m] * sKs[m];
            den[tid] = a * sc + (float)Nn;
        }
        __syncthreads();
#pragma unroll
        for (int nt = 0; nt < 4; nt++) {
            int c0 = cw * 32 + nt * 8 + t * 2;
            int r0 = rw * 16 + g, r1 = r0 + 8;
            if (row0 + r0 < Nn) {
                float dn = den[r0];
                float n0 = acc[nt][0] * sc + sVs[c0], n1 = acc[nt][1] * sc + sVs[c0 + 1];
                *(float2*)&g_out[(size_t)(row0 + r0) * HD + h * 64 + c0] = make_float2(n0 / dn, n1 / dn);
            }
            if (row0 + r1 < Nn) {
                float dn = den[r1];
                float n0 = acc[nt][2] * sc + sVs[c0], n1 = acc[nt][3] * sc + sVs[c0 + 1];
                *(float2*)&g_out[(size_t)(row0 + r1) * HD + h * 64 + c0] = make_float2(n0 / dn, n1 / dn);
            }
        }
    }
}

// ---------------- fused GCN gather + head-mean + residual + LN + split ----------------
__global__ void k_gcnc(const float* __restrict__ lnw, const float* __restrict__ lnb) {
    int lane = threadIdx.x & 31;
    int n = blockIdx.x * 8 + (threadIdx.x >> 5);
    if (n >= Nn) return;
    int p0 = g_ptr[n], p1 = g_ptr[n + 1];
    float rn = g_rsq[n];
    float4 acc = make_float4(0.f, 0.f, 0.f, 0.f);
    int e = p0;
    for (; e + 2 <= p1; e += 2) {
        int r0 = g_erow[e], r1 = g_erow[e + 1];
        float w0 = rn * g_rsq[r0], w1 = rn * g_rsq[r1];
        float4 va = *(const float4*)&g_v[(size_t)r0 * HD + lane * 4];
        float4 vb = *(const float4*)&g_v[(size_t)r1 * HD + lane * 4];
        acc.x += w0 * va.x + w1 * vb.x; acc.y += w0 * va.y + w1 * vb.y;
        acc.z += w0 * va.z + w1 * vb.z; acc.w += w0 * va.w + w1 * vb.w;
    }
    if (e < p1) {
        int r0 = g_erow[e];
        float w0 = rn * g_rsq[r0];
        float4 va = *(const float4*)&g_v[(size_t)r0 * HD + lane * 4];
        acc.x += w0 * va.x; acc.y += w0 * va.y; acc.z += w0 * va.z; acc.w += w0 * va.w;
    }
    float4 o = *(const float4*)&g_out[(size_t)n * HD + lane * 4];
    o.x += acc.x; o.y += acc.y; o.z += acc.z; o.w += acc.w;
    float4 m4;
    m4.x = 0.5f * (o.x + __shfl_xor_sync(FULL, o.x, 16));
    m4.y = 0.5f * (o.y + __shfl_xor_sync(FULL, o.y, 16));
    m4.z = 0.5f * (o.z + __shfl_xor_sync(FULL, o.z, 16));
    m4.w = 0.5f * (o.w + __shfl_xor_sync(FULL, o.w, 16));
    if (lane < 16) {
        float4 pv = *(const float4*)&g_prev[(size_t)n * HIDD + lane * 4];
        float4 hv;
        hv.x = 0.5f * m4.x + 0.5f * pv.x;
        hv.y = 0.5f * m4.y + 0.5f * pv.y;
        hv.z = 0.5f * m4.z + 0.5f * pv.z;
        hv.w = 0.5f * m4.w + 0.5f * pv.w;
        float s = hv.x + hv.y + hv.z + hv.w;
        float sq = hv.x * hv.x + hv.y * hv.y + hv.z * hv.z + hv.w * hv.w;
#pragma unroll
        for (int o2 = 1; o2 < 16; o2 <<= 1) {
            s += __shfl_xor_sync(0x0000ffffu, s, o2);
            sq += __shfl_xor_sync(0x0000ffffu, sq, o2);
        }
        float mu = s * 0.015625f;
        float var = sq * 0.015625f - mu * mu;
        float rs = rsqrtf(var + EPSL);
        float4 lw = *(const float4*)&lnw[lane * 4];
        float4 lb = *(const float4*)&lnb[lane * 4];
        float4 y;
        y.x = (hv.x - mu) * rs * lw.x + lb.x;
        y.y = (hv.y - mu) * rs * lw.y + lb.y;
        y.z = (hv.z - mu) * rs * lw.z + lb.z;
        y.w = (hv.w - mu) * rs * lw.w + lb.w;
        *(float4*)&g_h[(size_t)n * HIDD + lane * 4] = y;
        *(float4*)&g_prev[(size_t)n * HIDD + lane * 4] = y;
        unsigned h0, l0, h1, l1;
        bsplit2(y.x, y.y, h0, l0);
        bsplit2(y.z, y.w, h1, l1);
        *(uint2*)&g_hh[(size_t)n * 32 + lane * 2] = make_uint2(h0, h1);
        *(uint2*)&g_hl[(size_t)n * 32 + lane * 2] = make_uint2(l0, l1);
    }
}

// ---------------- final projection ----------------
__global__ void k_fco(const float* __restrict__ w, const float* __restrict__ b,
                      float* __restrict__ out) {
    __shared__ float ws[64][40];
    __shared__ float hs[64][65];
    int tid = threadIdx.x;
    int row0 = blockIdx.x * 64;
    for (int l = tid; l < 64 * 40; l += 256) ws[l / 40][l % 40] = w[l];
#pragma unroll
    for (int l = 0; l < 4; l++) {
        int lin = tid + l * 256;
        int r = lin >> 4, c4 = lin & 15;
        int gr = row0 + r; if (gr >= Nn) gr = Nn - 1;
        float4 v = *(const float4*)&g_h[(size_t)gr * HIDD + c4 * 4];
        hs[r][c4 * 4 + 0] = v.x; hs[r][c4 * 4 + 1] = v.y;
        hs[r][c4 * 4 + 2] = v.z; hs[r][c4 * 4 + 3] = v.w;
    }
    __syncthreads();
    int r = tid & 63, cg = tid >> 6;
    float acc[10] = {};
#pragma unroll
    for (int kk = 0; kk < 64; kk++) {
        float a = hs[r][kk];
        const float* wr = &ws[kk][cg * 10];
#pragma unroll
        for (int j = 0; j < 10; j++) acc[j] += a * wr[j];
    }
    int gr = row0 + r;
    if (gr < Nn) {
#pragma unroll
        for (int j = 0; j < 10; j++)
            out[(size_t)gr * CC + cg * 10 + j] = acc[j] + b[cg * 10 + j];
    }
}

// ---------------- launcher ----------------
extern "C" void kernel_launch(void* const* d_in, const int* in_sizes, int n_in,
                              void* d_out, int out_size) {
    (void)in_sizes; (void)n_in; (void)out_size;
    const float* x     = (const float*)d_in[0];
    const int*   ei    = (const int*)d_in[1];
    const float* fc0_w = (const float*)d_in[2];
    const float* fc0_b = (const float*)d_in[3];
    const float* ln_w  = (const float*)d_in[4];
    const float* ln_b  = (const float*)d_in[5];
    const float* Wq    = (const float*)d_in[6];
    const float* Wk    = (const float*)d_in[7];
    const float* Wv    = (const float*)d_in[8];
    const float* bq    = (const float*)d_in[9];
    const float* bk    = (const float*)d_in[10];
    const float* bv    = (const float*)d_in[11];
    const float* fco_w = (const float*)d_in[12];
    const float* fco_b = (const float*)d_in[13];
    float* out = (float*)d_out;

    const int GB = (Nn + 63) / 64;      // 1563
    const int NB = (Nn + 255) / 256;    // 391
    const int EB = (Ee + 255) / 256;    // 3125

    // order chosen so launch #6 (ncu -s 5 -c 1) is k_qkv
    k_prep<<<128, 256>>>(fc0_w, Wq, Wk, Wv);                   // 1
    k_fc0<<<GB, 256>>>(x, fc0_b, ln_w, ln_b);                  // 2
    k_zcnt<<<NB, 256>>>();                                     // 3
    k_count<<<EB, 256>>>(ei + Ee);                             // 4
    k_zero_red<<<34, 256>>>();                                 // 5
    k_qkv<<<GB, 256>>>(0, bq, bk, bv);                         // 6  <- profiled
    k_rsqk<<<NB, 256>>>();                                     // 7
    k_scan1<<<NB, 256>>>();                                    // 8
    k_scan2<<<1, 512>>>();                                     // 9
    k_scan3<<<NB, 256>>>();                                    // 10
    k_fill<<<EB, 256>>>(ei, ei + Ee);                          // 11
    k_reduce<<<128, 256>>>();                                  // 12
    k_attn<<<GB, 256>>>();                                     // 13
    k_gcnc<<<(Nn + 7) / 8, 256>>>(ln_w + HIDD, ln_b + HIDD);   // 14
    k_zero_red<<<34, 256>>>();                                 // 15
    k_qkv<<<GB, 256>>>(1, bq + HD, bk + HD, bv + HD);          // 16
    k_reduce<<<128, 256>>>();                                  // 17
    k_attn<<<GB, 256>>>();                                     // 18
    k_gcnc<<<(Nn + 7) / 8, 256>>>(ln_w + 2 * HIDD, ln_b + 2 * HIDD); // 19
    k_fco<<<GB, 256>>>(fco_w, fco_b, out);                     // 20
}

// round 5
// speedup vs baseline: 1.4923x; 1.2912x over previous
#include <cuda_runtime.h>

#define Nn    100000
#define Ee    800000
#define INF   256
#define HIDD  64
#define HD    128
#define CC    40
#define EPSL  1e-5f
#define FULL  0xffffffffu
#define GBLK  1563

// ---------------- scratch ----------------
__device__ float g_h[Nn * HIDD];
__device__ float g_prev[Nn * HIDD];
__device__ float g_v[Nn * HD];
__device__ float g_vm[Nn * HIDD];          // head-mean of v (fp32)
__device__ float g_rsq[Nn];
__device__ float g_kvs[2 * HIDD * HIDD];
__device__ float g_sumK[HD];
__device__ float g_sumV[HD];
__device__ float g_sums[2];
__device__ int   g_cnt[Nn];
__device__ int   g_ptr[Nn + 1];
__device__ int   g_cur[Nn];
__device__ int   g_erow[Ee];
__device__ int   g_blk[512];
__device__ unsigned g_hh[Nn * 32];         // split-bf16 h hi (pairs along feature)
__device__ unsigned g_hl[Nn * 32];         // split-bf16 h lo
__device__ unsigned g_qp_unused[1];
__device__ unsigned g_qf[(size_t)GBLK * 4096];  // q in A-fragment order per 64-row block
__device__ unsigned g_kp[Nn * 64];         // k packed bf16 (pairs along feature)
__device__ unsigned g_kvsp[4608];          // kvs+sumK in B-fragment order [head][2304]
// pre-split weights in fragment order (2048 uints per 64x64 chunk)
__device__ unsigned g_w0h[8192], g_w0l[8192];
__device__ unsigned g_wfh[24576], g_wfl[24576];

// ---------------- bf16 helpers ----------------
__device__ __forceinline__ unsigned packbf2(float f0, float f1) {
    unsigned r; asm("cvt.rn.bf16x2.f32 %0, %1, %2;" : "=r"(r) : "f"(f1), "f"(f0)); return r;
}
__device__ __forceinline__ void bsplit2(float f0, float f1, unsigned& h, unsigned& l) {
    h = packbf2(f0, f1);
    float h0 = __uint_as_float(h << 16);
    float h1 = __uint_as_float(h & 0xffff0000u);
    l = packbf2(f0 - h0, f1 - h1);
}
__device__ __forceinline__ void mma16(float* d, const unsigned* a, const unsigned* b) {
    asm volatile("mma.sync.aligned.m16n8k16.row.col.f32.bf16.bf16.f32 "
        "{%0,%1,%2,%3}, {%4,%5,%6,%7}, {%8,%9}, {%0,%1,%2,%3};"
        : "+f"(d[0]), "+f"(d[1]), "+f"(d[2]), "+f"(d[3])
        : "r"(a[0]), "r"(a[1]), "r"(a[2]), "r"(a[3]), "r"(b[0]), "r"(b[1]));
}

// frag position for A element pair: row r (0..63), pair p (0..31)
__device__ __forceinline__ int aFragPos(int r, int p) {
    return (((r >> 4) * 4 + (p >> 3)) * 32 + ((r & 7) * 4 + (p & 3))) * 4
           + ((r >> 3) & 1) + 2 * ((p >> 2) & 1);
}

// ---------------- weight pre-split ----------------
__global__ void k_prep(const float* __restrict__ fc0_w, const float* __restrict__ Wq,
                       const float* __restrict__ Wk, const float* __restrict__ Wv) {
    int id = blockIdx.x * 256 + threadIdx.x;   // 32768 total
    if (id < 8192) {
        int kc = id >> 11, rem = id & 2047;
        int reg = rem & 1, lane = (rem >> 1) & 31, ntg = (rem >> 6) & 7, kt = rem >> 9;
        int t = lane & 3, gg = lane >> 2;
        int k = kc * 64 + kt * 16 + reg * 8 + 2 * t;
        int c = ntg * 8 + gg;
        float f0 = fc0_w[k * HIDD + c], f1 = fc0_w[(k + 1) * HIDD + c];
        unsigned h, l; bsplit2(f0, f1, h, l);
        g_w0h[id] = h; g_w0l[id] = l;
    } else if (id < 32768) {
        int id2 = id - 8192;
        int layer = id2 / 12288, r3 = id2 % 12288;
        int mat = r3 >> 12, cc2 = (r3 >> 11) & 1, rem = r3 & 2047;
        int reg = rem & 1, lane = (rem >> 1) & 31, ntg = (rem >> 6) & 7, kt = rem >> 9;
        int t = lane & 3, gg = lane >> 2;
        const float* W = (mat == 0 ? Wq : (mat == 1 ? Wk : Wv)) + (size_t)layer * HIDD * HD;
        int k = kt * 16 + reg * 8 + 2 * t;
        int cg = cc2 * 64 + ntg * 8 + gg;
        float f0 = W[k * HD + cg], f1 = W[(k + 1) * HD + cg];
        unsigned h, l; bsplit2(f0, f1, h, l);
        g_wfh[id2] = h; g_wfl[id2] = l;
    }
}

// ---------------- fc0 (unchanged from R4) ----------------
__global__ void k_fc0(const float* __restrict__ x, const float* __restrict__ bias,
                      const float* __restrict__ lnw, const float* __restrict__ lnb) {
    __shared__ __align__(16) unsigned sm[8192];
    float* scr = (float*)sm;
    int tid = threadIdx.x, lane = tid & 31, warp = tid >> 5;
    int rw = warp & 3, cw = warp >> 2, g = lane >> 2, t = lane & 3;
    int row0 = blockIdx.x * 64;
    float acc[4][4] = {};
    for (int kc = 0; kc < 4; kc++) {
        __syncthreads();
#pragma unroll
        for (int i = 0; i < 8; i++) {
            int idx = tid + i * 256;
            sm[4096 + idx] = g_w0h[kc * 2048 + idx];
            sm[6144 + idx] = g_w0l[kc * 2048 + idx];
        }
#pragma unroll
        for (int i = 0; i < 4; i++) {
            int idx = tid + i * 256;
            int r = idx >> 4, q4 = idx & 15;
            int gr = row0 + r;
            float4 v = make_float4(0.f, 0.f, 0.f, 0.f);
            if (gr < Nn) v = *(const float4*)&x[(size_t)gr * INF + kc * 64 + q4 * 4];
            unsigned h0, l0, h1, l1;
            bsplit2(v.x, v.y, h0, l0);
            bsplit2(v.z, v.w, h1, l1);
            int pos0 = aFragPos(r, q4 * 2);
            int pos1 = aFragPos(r, q4 * 2 + 1);
            sm[pos0] = h0; sm[2048 + pos0] = l0;
            sm[pos1] = h1; sm[2048 + pos1] = l1;
        }
        __syncthreads();
#pragma unroll
        for (int kt = 0; kt < 4; kt++) {
            uint4 ah = *(uint4*)&sm[((rw * 4 + kt) * 32 + lane) * 4];
            uint4 al = *(uint4*)&sm[2048 + ((rw * 4 + kt) * 32 + lane) * 4];
#pragma unroll
            for (int nt = 0; nt < 4; nt++) {
                int ntg = cw * 4 + nt;
                uint2 bh = *(uint2*)&sm[4096 + ((kt * 8 + ntg) * 32 + lane) * 2];
                uint2 bl = *(uint2*)&sm[6144 + ((kt * 8 + ntg) * 32 + lane) * 2];
                mma16(acc[nt], (const unsigned*)&ah, (const unsigned*)&bh);
                mma16(acc[nt], (const unsigned*)&ah, (const unsigned*)&bl);
                mma16(acc[nt], (const unsigned*)&al, (const unsigned*)&bh);
            }
        }
    }
    __syncthreads();
#pragma unroll
    for (int nt = 0; nt < 4; nt++) {
        int c0 = cw * 32 + nt * 8 + t * 2;
        float b0v = bias[c0], b1v = bias[c0 + 1];
        int r0 = rw * 16 + g, r1 = r0 + 8;
        scr[r0 * 68 + c0] = acc[nt][0] + b0v; scr[r0 * 68 + c0 + 1] = acc[nt][1] + b1v;
        scr[r1 * 68 + c0] = acc[nt][2] + b0v; scr[r1 * 68 + c0 + 1] = acc[nt][3] + b1v;
    }
    __syncthreads();
    int r = tid >> 2, sub = tid & 3;
    float vbuf[16];
    float s = 0.f, sq = 0.f;
#pragma unroll
    for (int j = 0; j < 16; j++) { float v = scr[r * 68 + sub * 16 + j]; vbuf[j] = v; s += v; sq += v * v; }
    s += __shfl_xor_sync(FULL, s, 1); sq += __shfl_xor_sync(FULL, sq, 1);
    s += __shfl_xor_sync(FULL, s, 2); sq += __shfl_xor_sync(FULL, sq, 2);
    float mu = s * 0.015625f;
    float var = sq * 0.015625f - mu * mu;
    float rs = rsqrtf(var + EPSL);
    int gr = row0 + r;
    if (gr < Nn) {
        float y[16];
#pragma unroll
        for (int j = 0; j < 16; j++) {
            int c = sub * 16 + j;
            float yy = (vbuf[j] - mu) * rs * lnw[c] + lnb[c];
            yy = fmaxf(yy, 0.f);
            y[j] = yy;
            g_prev[(size_t)gr * HIDD + c] = yy;
        }
#pragma unroll
        for (int jp = 0; jp < 8; jp++) {
            unsigned h, l; bsplit2(y[2 * jp], y[2 * jp + 1], h, l);
            g_hh[(size_t)gr * 32 + sub * 8 + jp] = h;
            g_hl[(size_t)gr * 32 + sub * 8 + jp] = l;
        }
    }
}

// ---------------- CSR build ----------------
__global__ void k_zcnt() { int i = blockIdx.x * 256 + threadIdx.x; if (i < Nn) g_cnt[i] = 0; }
__global__ void k_count(const int* __restrict__ col) {
    int e = blockIdx.x * 256 + threadIdx.x;
    if (e < Ee) atomicAdd(&g_cnt[col[e]], 1);
}
__global__ void k_rsqk() {
    int i = blockIdx.x * 256 + threadIdx.x;
    if (i < Nn) { int c = g_cnt[i]; g_rsq[i] = c > 0 ? rsqrtf((float)c) : 0.f; }
}
__device__ __forceinline__ int blockScanIncl(int val, int* wsum) {
    int lane = threadIdx.x & 31, wid = threadIdx.x >> 5;
#pragma unroll
    for (int o = 1; o < 32; o <<= 1) {
        int n = __shfl_up_sync(FULL, val, o);
        if (lane >= o) val += n;
    }
    if (lane == 31) wsum[wid] = val;
    __syncthreads();
    if (wid == 0) {
        int nw = blockDim.x >> 5;
        int w = (lane < nw) ? wsum[lane] : 0;
#pragma unroll
        for (int o = 1; o < 32; o <<= 1) {
            int n = __shfl_up_sync(FULL, w, o);
            if (lane >= o) w += n;
        }
        wsum[lane] = w;
    }
    __syncthreads();
    return val + (wid > 0 ? wsum[wid - 1] : 0);
}
__global__ void k_scan1() {
    __shared__ int wsum[32];
    int i = blockIdx.x * 256 + threadIdx.x;
    int v = (i < Nn) ? g_cnt[i] : 0;
    int incl = blockScanIncl(v, wsum);
    if (i < Nn) g_ptr[i] = incl - v;
    if (threadIdx.x == 255) g_blk[blockIdx.x] = incl;
}
__global__ void k_scan2() {
    __shared__ int wsum[32];
    const int NB = (Nn + 255) / 256;
    int v = (threadIdx.x < NB) ? g_blk[threadIdx.x] : 0;
    int incl = blockScanIncl(v, wsum);
    if (threadIdx.x < NB) g_blk[threadIdx.x] = incl - v;
}
__global__ void k_scan3() {
    int i = blockIdx.x * 256 + threadIdx.x;
    if (i < Nn) {
        int p = g_ptr[i] + g_blk[i >> 8];
        g_ptr[i] = p; g_cur[i] = p;
    }
    if (i == 0) g_ptr[Nn] = Ee;
}
__global__ void k_fill(const int* __restrict__ row, const int* __restrict__ col) {
    int e = blockIdx.x * 256 + threadIdx.x;
    if (e < Ee) {
        int c = col[e];
        int p = atomicAdd(&g_cur[c], 1);
        g_erow[p] = row[e];
    }
}

// ---------------- per-layer reduction zero ----------------
__global__ void k_zero_red() {
    int i = blockIdx.x * blockDim.x + threadIdx.x;
    int stride = gridDim.x * blockDim.x;
    for (int j = i; j < 8192; j += stride) g_kvs[j] = 0.f;
    if (i < HD) { g_sumK[i] = 0.f; g_sumV[i] = 0.f; }
    if (i < 2) g_sums[i] = 0.f;
}

// ---------------- QKV GEMM: frag mainloop + staged coalesced epilogues ----------------
__global__ void k_qkv(int layer, const float* __restrict__ bq,
                      const float* __restrict__ bk, const float* __restrict__ bv) {
    __shared__ __align__(16) unsigned sm[8704];   // AH 2048 | AL 2048 | B/scr 4608
    __shared__ float sK[128], sV[128];
    float* scr2 = (float*)&sm[4096];              // 4608 floats (pad-72 rows)
    int tid = threadIdx.x, lane = tid & 31, warp = tid >> 5;
    int rw = warp & 3, cw = warp >> 2, g = lane >> 2, t = lane & 3;
    int row0 = blockIdx.x * 64;
    const unsigned* wfh = g_wfh + layer * 12288;
    const unsigned* wfl = g_wfl + layer * 12288;
    if (tid < 128) { sK[tid] = 0.f; sV[tid] = 0.f; }
#pragma unroll
    for (int i = 0; i < 8; i++) {
        int idx = tid + i * 256;
        int r = idx >> 5, p = idx & 31;
        int gr = row0 + r;
        unsigned hv = 0, lv = 0;
        if (gr < Nn) { hv = g_hh[(size_t)gr * 32 + p]; lv = g_hl[(size_t)gr * 32 + p]; }
        int pos = aFragPos(r, p);
        sm[pos] = hv; sm[2048 + pos] = lv;
    }
    bool rowok0 = (row0 + rw * 16 + g) < Nn;
    bool rowok1 = (row0 + rw * 16 + g + 8) < Nn;
    float q2 = 0.f, k2 = 0.f;
    for (int ch = 0; ch < 6; ch++) {
        int mat = ch >> 1, cc2 = ch & 1;
        const float* B = mat == 0 ? bq : (mat == 1 ? bk : bv);
        bool split = (mat == 2);
        __syncthreads();
#pragma unroll
        for (int i = 0; i < 8; i++) {
            int idx = tid + i * 256;
            sm[4096 + idx] = wfh[ch * 2048 + idx];
            sm[6144 + idx] = wfl[ch * 2048 + idx];
        }
        __syncthreads();
        float acc[4][4] = {};
#pragma unroll
        for (int kt = 0; kt < 4; kt++) {
            uint4 ah = *(uint4*)&sm[((rw * 4 + kt) * 32 + lane) * 4];
            uint4 al;
            if (split) al = *(uint4*)&sm[2048 + ((rw * 4 + kt) * 32 + lane) * 4];
#pragma unroll
            for (int nt = 0; nt < 4; nt++) {
                int ntg = cw * 4 + nt;
                uint2 bh = *(uint2*)&sm[4096 + ((kt * 8 + ntg) * 32 + lane) * 2];
                mma16(acc[nt], (const unsigned*)&ah, (const unsigned*)&bh);
                if (split) {
                    uint2 bl = *(uint2*)&sm[6144 + ((kt * 8 + ntg) * 32 + lane) * 2];
                    mma16(acc[nt], (const unsigned*)&ah, (const unsigned*)&bl);
                    mma16(acc[nt], (const unsigned*)&al, (const unsigned*)&bh);
                }
            }
        }
        // bias + reductions (register side)
#pragma unroll
        for (int nt = 0; nt < 4; nt++) {
            int cgl = cc2 * 64 + cw * 32 + nt * 8 + t * 2;
            float b0v = B[cgl], b1v = B[cgl + 1];
            acc[nt][0] += b0v; acc[nt][1] += b1v;
            acc[nt][2] += b0v; acc[nt][3] += b1v;
            float v00 = rowok0 ? acc[nt][0] : 0.f, v01 = rowok0 ? acc[nt][1] : 0.f;
            float v10 = rowok1 ? acc[nt][2] : 0.f, v11 = rowok1 ? acc[nt][3] : 0.f;
            if (mat == 0) {
                q2 += v00 * v00 + v01 * v01 + v10 * v10 + v11 * v11;
            } else {
                if (mat == 1) k2 += v00 * v00 + v01 * v01 + v10 * v10 + v11 * v11;
                float c0s = v00 + v10, c1s = v01 + v11;
                c0s += __shfl_xor_sync(FULL, c0s, 4);  c1s += __shfl_xor_sync(FULL, c1s, 4);
                c0s += __shfl_xor_sync(FULL, c0s, 8);  c1s += __shfl_xor_sync(FULL, c1s, 8);
                c0s += __shfl_xor_sync(FULL, c0s, 16); c1s += __shfl_xor_sync(FULL, c1s, 16);
                if (g == 0) {
                    float* sd = (mat == 1) ? sK : sV;
                    atomicAdd(&sd[cgl], c0s);
                    atomicAdd(&sd[cgl + 1], c1s);
                }
            }
        }
        __syncthreads();   // mainloop B reads done -> scr2 may overwrite
#pragma unroll
        for (int nt = 0; nt < 4; nt++) {
            int c0 = cw * 32 + nt * 8 + t * 2;
            int r0 = rw * 16 + g, r1 = r0 + 8;
            scr2[r0 * 72 + c0] = acc[nt][0]; scr2[r0 * 72 + c0 + 1] = acc[nt][1];
            scr2[r1 * 72 + c0] = acc[nt][2]; scr2[r1 * 72 + c0 + 1] = acc[nt][3];
        }
        __syncthreads();
        if (mat == 0) {
            // q -> fragment-order packed bf16 -> linear coalesced store
            unsigned rr[8]; int ps[8];
#pragma unroll
            for (int i = 0; i < 8; i++) {
                int idx = tid + i * 256;
                int r = idx >> 5, p = idx & 31;
                rr[i] = packbf2(scr2[r * 72 + 2 * p], scr2[r * 72 + 2 * p + 1]);
                ps[i] = aFragPos(r, p);
            }
            __syncthreads();
#pragma unroll
            for (int i = 0; i < 8; i++) sm[4096 + ps[i]] = rr[i];
            __syncthreads();
#pragma unroll
            for (int i = 0; i < 8; i++) {
                int idx = tid + i * 256;
                g_qf[(size_t)blockIdx.x * 4096 + cc2 * 2048 + idx] = sm[4096 + idx];
            }
        } else if (mat == 1) {
            // k -> packed bf16 linear (pairs along feature)
#pragma unroll
            for (int i = 0; i < 8; i++) {
                int idx = tid + i * 256;
                int r = idx >> 5, p = idx & 31;
                int gr = row0 + r;
                if (gr < Nn)
                    g_kp[(size_t)gr * 64 + cc2 * 32 + p] =
                        packbf2(scr2[r * 72 + 2 * p], scr2[r * 72 + 2 * p + 1]);
            }
        } else {
            // v -> fp32 float4 coalesced
#pragma unroll
            for (int i = 0; i < 4; i++) {
                int idx = tid + i * 256;
                int r = idx >> 4, c4 = idx & 15;
                int gr = row0 + r;
                if (gr < Nn)
                    *(float4*)&g_v[(size_t)gr * HD + cc2 * 64 + c4 * 4] =
                        *(float4*)&scr2[r * 72 + c4 * 4];
            }
        }
    }
#pragma unroll
    for (int o = 16; o > 0; o >>= 1) {
        q2 += __shfl_xor_sync(FULL, q2, o);
        k2 += __shfl_xor_sync(FULL, k2, o);
    }
    if (lane == 0) { atomicAdd(&g_sums[0], q2); atomicAdd(&g_sums[1], k2); }
    __syncthreads();
    if (tid < 128) { atomicAdd(&g_sumK[tid], sK[tid]); atomicAdd(&g_sumV[tid], sV[tid]); }
}

// ---------------- kvs = k^T v : frag-staged bf16 mma, emits g_vm ----------------
__global__ void k_reduce() {
    __shared__ __align__(16) unsigned kraw[2048];   // [n32][pair64]
    __shared__ __align__(16) float    vraw[4096];   // [n32][d128]
    __shared__ __align__(16) unsigned afr[2048];
    __shared__ __align__(16) unsigned bfr[2048];
    int tid = threadIdx.x, lane = tid & 31, warp = tid >> 5;
    int h = warp >> 2, mt = warp & 3;
    int t = lane & 3, g = lane >> 2;
    float acc[8][4] = {};
    const int NT = Nn / 32;   // 3125
    for (int tt = blockIdx.x; tt < NT; tt += gridDim.x) {
        __syncthreads();
#pragma unroll
        for (int i = 0; i < 2; i++) {
            int idx4 = tid + i * 256;
            int n = idx4 >> 4, p4 = idx4 & 15;
            *(uint4*)&kraw[n * 64 + p4 * 4] =
                *(const uint4*)&g_kp[(size_t)(tt * 32 + n) * 64 + p4 * 4];
        }
#pragma unroll
        for (int i = 0; i < 4; i++) {
            int idx4 = tid + i * 256;
            int n = idx4 >> 5, d4 = idx4 & 31;
            *(float4*)&vraw[n * 128 + d4 * 4] =
                *(const float4*)&g_v[(size_t)(tt * 32 + n) * HD + d4 * 4];
        }
        __syncthreads();
        // emit g_vm (head mean, fp32)
#pragma unroll
        for (int i = 0; i < 8; i++) {
            int idx = tid + i * 256;
            int n = idx >> 6, d = idx & 63;
            g_vm[(size_t)(tt * 32 + n) * 64 + d] =
                0.5f * (vraw[n * 128 + d] + vraw[n * 128 + 64 + d]);
        }
        // stage A frags (k^T): pairs along n
#pragma unroll
        for (int i = 0; i < 8; i++) {
            int idx = tid + i * 256;
            int j = idx & 3, ln = (idx >> 2) & 31, mtt = (idx >> 7) & 3,
                ks = (idx >> 9) & 1, hh = (idx >> 10) & 1;
            int lt = ln & 3, lg = ln >> 2;
            int m = mtt * 16 + lg + (j & 1) * 8;
            int n0 = ks * 16 + 2 * lt + (j >> 1) * 8;
            int hm = hh * 64 + m;
            unsigned u0 = kraw[n0 * 64 + (hm >> 1)];
            unsigned u1 = kraw[(n0 + 1) * 64 + (hm >> 1)];
            afr[idx] = __byte_perm(u0, u1, (hm & 1) ? 0x7632 : 0x5410);
        }
        // stage B frags (v): pairs along n
#pragma unroll
        for (int i = 0; i < 8; i++) {
            int idx = tid + i * 256;
            int reg = idx & 1, ln = (idx >> 1) & 31, ntg = (idx >> 6) & 7,
                ks = (idx >> 9) & 1, hh = (idx >> 10) & 1;
            int lt = ln & 3, lg = ln >> 2;
            int d = ntg * 8 + lg;
            int n0 = ks * 16 + 2 * lt + reg * 8;
            bfr[idx] = packbf2(vraw[n0 * 128 + hh * 64 + d],
                               vraw[(n0 + 1) * 128 + hh * 64 + d]);
        }
        __syncthreads();
#pragma unroll
        for (int ks = 0; ks < 2; ks++) {
            uint4 a = *(uint4*)&afr[((h * 2 + ks) * 4 + mt) * 128 + lane * 4];
#pragma unroll
            for (int nt = 0; nt < 8; nt++) {
                uint2 b = *(uint2*)&bfr[(((h * 2 + ks) * 8 + nt) * 32 + lane) * 2];
                mma16(acc[nt], (const unsigned*)&a, (const unsigned*)&b);
            }
        }
    }
#pragma unroll
    for (int nt = 0; nt < 8; nt++) {
        int c0 = nt * 8 + 2 * t;
        int r0 = mt * 16 + g, r1 = r0 + 8;
        atomicAdd(&g_kvs[h * 4096 + r0 * 64 + c0],     acc[nt][0]);
        atomicAdd(&g_kvs[h * 4096 + r0 * 64 + c0 + 1], acc[nt][1]);
        atomicAdd(&g_kvs[h * 4096 + r1 * 64 + c0],     acc[nt][2]);
        atomicAdd(&g_kvs[h * 4096 + r1 * 64 + c0 + 1], acc[nt][3]);
    }
}

// ---------------- pack kvs (+ sumK as col 64) into B-fragment order ----------------
__global__ void k_pkvs() {
    int gid = blockIdx.x * 256 + threadIdx.x;
    if (gid >= 4608) return;
    int h = gid / 2304, rem = gid % 2304;
    int reg = rem & 1, ln = (rem >> 1) & 31, ntg = (rem >> 6) % 9, kt = rem / 576;
    int lt = ln & 3, lg = ln >> 2;
    int m = kt * 16 + reg * 8 + 2 * lt;
    unsigned val;
    if (ntg < 8) {
        int c = ntg * 8 + lg;
        val = packbf2(g_kvs[h * 4096 + m * 64 + c], g_kvs[h * 4096 + (m + 1) * 64 + c]);
    } else {
        val = (lg == 0) ? packbf2(g_sumK[h * 64 + m], g_sumK[h * 64 + m + 1]) : 0u;
    }
    g_kvsp[gid] = val;
}

// ---------------- fused attention + GCN gather + combine + LN + pack ----------------
__global__ void k_attnc(const float* __restrict__ lnw, const float* __restrict__ lnb) {
    __shared__ float scrf[64 * 68];
    __shared__ float sVs[128];
    __shared__ float denS[128];
    int tid = threadIdx.x, lane = tid & 31, warp = tid >> 5;
    int rw = warp & 3, cw = warp >> 2, g = lane >> 2, t = lane & 3;
    int row0 = blockIdx.x * 64;
    float sc = rsqrtf(g_sums[0] * g_sums[1]);
    if (tid < 128) sVs[tid] = g_sumV[tid];
    float acc0[5][4] = {}, acc1[5][4] = {};
    int ntn = 4 + cw;
#pragma unroll
    for (int kt = 0; kt < 4; kt++) {
        uint4 a = *(const uint4*)&g_qf[(size_t)blockIdx.x * 4096 + ((rw * 4 + kt) * 32 + lane) * 4];
#pragma unroll
        for (int nt = 0; nt < 5; nt++) {
            if (nt < ntn) {
                int ntg = cw * 4 + nt;
                uint2 b = *(const uint2*)&g_kvsp[((kt * 9 + ntg) * 32 + lane) * 2];
                mma16(acc0[nt], (const unsigned*)&a, (const unsigned*)&b);
            }
        }
    }
#pragma unroll
    for (int kt = 0; kt < 4; kt++) {
        uint4 a = *(const uint4*)&g_qf[(size_t)blockIdx.x * 4096 + 2048 + ((rw * 4 + kt) * 32 + lane) * 4];
#pragma unroll
        for (int nt = 0; nt < 5; nt++) {
            if (nt < ntn) {
                int ntg = cw * 4 + nt;
                uint2 b = *(const uint2*)&g_kvsp[2304 + ((kt * 9 + ntg) * 32 + lane) * 2];
                mma16(acc1[nt], (const unsigned*)&a, (const unsigned*)&b);
            }
        }
    }
    if (cw == 1 && t == 0) {
        int r0 = rw * 16 + g;
        denS[r0]          = acc0[4][0] * sc + (float)Nn;
        denS[r0 + 8]      = acc0[4][2] * sc + (float)Nn;
        denS[64 + r0]     = acc1[4][0] * sc + (float)Nn;
        denS[64 + r0 + 8] = acc1[4][2] * sc + (float)Nn;
    }
    __syncthreads();
#pragma unroll
    for (int nt = 0; nt < 4; nt++) {
        int c = cw * 32 + nt * 8 + 2 * t;
        int r0 = rw * 16 + g, r1 = r0 + 8;
        float d00 = denS[r0], d01 = denS[r1];
        float d10 = denS[64 + r0], d11 = denS[64 + r1];
        scrf[r0 * 68 + c]     = 0.5f * ((acc0[nt][0] * sc + sVs[c])     / d00 + (acc1[nt][0] * sc + sVs[64 + c])     / d10);
        scrf[r0 * 68 + c + 1] = 0.5f * ((acc0[nt][1] * sc + sVs[c + 1]) / d00 + (acc1[nt][1] * sc + sVs[64 + c + 1]) / d10);
        scrf[r1 * 68 + c]     = 0.5f * ((acc0[nt][2] * sc + sVs[c])     / d01 + (acc1[nt][2] * sc + sVs[64 + c])     / d11);
        scrf[r1 * 68 + c + 1] = 0.5f * ((acc0[nt][3] * sc + sVs[c + 1]) / d01 + (acc1[nt][3] * sc + sVs[64 + c + 1]) / d11);
    }
    __syncthreads();
    // gather + combine + LN : half-warp per node, 4 passes
    int half = lane >> 4, hl = lane & 15;
#pragma unroll
    for (int pass = 0; pass < 4; pass++) {
        int nl = pass * 16 + warp * 2 + half;
        int n = row0 + nl;
        if (n < Nn) {
            int p0 = g_ptr[n], p1 = g_ptr[n + 1];
            float rn = g_rsq[n];
            float ax = 0.f, ay = 0.f, az = 0.f, aw = 0.f;
            int e = p0;
            for (; e + 2 <= p1; e += 2) {
                int r0 = g_erow[e], r1 = g_erow[e + 1];
                float w0 = rn * g_rsq[r0], w1 = rn * g_rsq[r1];
                float4 va = *(const float4*)&g_vm[(size_t)r0 * 64 + hl * 4];
                float4 vb = *(const float4*)&g_vm[(size_t)r1 * 64 + hl * 4];
                ax += w0 * va.x + w1 * vb.x; ay += w0 * va.y + w1 * vb.y;
                az += w0 * va.z + w1 * vb.z; aw += w0 * va.w + w1 * vb.w;
            }
            if (e < p1) {
                int r0 = g_erow[e];
                float w0 = rn * g_rsq[r0];
                float4 va = *(const float4*)&g_vm[(size_t)r0 * 64 + hl * 4];
                ax += w0 * va.x; ay += w0 * va.y; az += w0 * va.z; aw += w0 * va.w;
            }
            float4 ov = *(const float4*)&scrf[nl * 68 + hl * 4];
            float4 pv = *(const float4*)&g_prev[(size_t)n * HIDD + hl * 4];
            float4 hv;
            hv.x = 0.5f * (ov.x + ax) + 0.5f * pv.x;
            hv.y = 0.5f * (ov.y + ay) + 0.5f * pv.y;
            hv.z = 0.5f * (ov.z + az) + 0.5f * pv.z;
            hv.w = 0.5f * (ov.w + aw) + 0.5f * pv.w;
            float s = hv.x + hv.y + hv.z + hv.w;
            float sq = hv.x * hv.x + hv.y * hv.y + hv.z * hv.z + hv.w * hv.w;
#pragma unroll
            for (int o = 1; o < 16; o <<= 1) {
                s += __shfl_xor_sync(FULL, s, o);
                sq += __shfl_xor_sync(FULL, sq, o);
            }
            float mu = s * 0.015625f;
            float var = sq * 0.015625f - mu * mu;
            float rs = rsqrtf(var + EPSL);
            float4 lw = *(const float4*)&lnw[hl * 4];
            float4 lb = *(const float4*)&lnb[hl * 4];
            float4 y;
            y.x = (hv.x - mu) * rs * lw.x + lb.x;
            y.y = (hv.y - mu) * rs * lw.y + lb.y;
            y.z = (hv.z - mu) * rs * lw.z + lb.z;
            y.w = (hv.w - mu) * rs * lw.w + lb.w;
            *(float4*)&g_h[(size_t)n * HIDD + hl * 4] = y;
            *(float4*)&g_prev[(size_t)n * HIDD + hl * 4] = y;
            unsigned h0, l0, h1, l1;
            bsplit2(y.x, y.y, h0, l0);
            bsplit2(y.z, y.w, h1, l1);
            *(uint2*)&g_hh[(size_t)n * 32 + hl * 2] = make_uint2(h0, h1);
            *(uint2*)&g_hl[(size_t)n * 32 + hl * 2] = make_uint2(l0, l1);
        }
    }
}

// ---------------- final projection ----------------
__global__ void k_fco(const float* __restrict__ w, const float* __restrict__ b,
                      float* __restrict__ out) {
    __shared__ float ws[64][40];
    __shared__ float hs[64][65];
    int tid = threadIdx.x;
    int row0 = blockIdx.x * 64;
    for (int l = tid; l < 64 * 40; l += 256) ws[l / 40][l % 40] = w[l];
#pragma unroll
    for (int l = 0; l < 4; l++) {
        int lin = tid + l * 256;
        int r = lin >> 4, c4 = lin & 15;
        int gr = row0 + r; if (gr >= Nn) gr = Nn - 1;
        float4 v = *(const float4*)&g_h[(size_t)gr * HIDD + c4 * 4];
        hs[r][c4 * 4 + 0] = v.x; hs[r][c4 * 4 + 1] = v.y;
        hs[r][c4 * 4 + 2] = v.z; hs[r][c4 * 4 + 3] = v.w;
    }
    __syncthreads();
    int r = tid & 63, cg = tid >> 6;
    float acc[10] = {};
#pragma unroll
    for (int kk = 0; kk < 64; kk++) {
        float a = hs[r][kk];
        const float* wr = &ws[kk][cg * 10];
#pragma unroll
        for (int j = 0; j < 10; j++) acc[j] += a * wr[j];
    }
    int gr = row0 + r;
    if (gr < Nn) {
#pragma unroll
        for (int j = 0; j < 10; j++)
            out[(size_t)gr * CC + cg * 10 + j] = acc[j] + b[cg * 10 + j];
    }
}

// ---------------- launcher ----------------
extern "C" void kernel_launch(void* const* d_in, const int* in_sizes, int n_in,
                              void* d_out, int out_size) {
    (void)in_sizes; (void)n_in; (void)out_size;
    const float* x     = (const float*)d_in[0];
    const int*   ei    = (const int*)d_in[1];
    const float* fc0_w = (const float*)d_in[2];
    const float* fc0_b = (const float*)d_in[3];
    const float* ln_w  = (const float*)d_in[4];
    const float* ln_b  = (const float*)d_in[5];
    const float* Wq    = (const float*)d_in[6];
    const float* Wk    = (const float*)d_in[7];
    const float* Wv    = (const float*)d_in[8];
    const float* bq    = (const float*)d_in[9];
    const float* bk    = (const float*)d_in[10];
    const float* bv    = (const float*)d_in[11];
    const float* fco_w = (const float*)d_in[12];
    const float* fco_b = (const float*)d_in[13];
    float* out = (float*)d_out;

    const int GB = GBLK;                // 1563
    const int NB = (Nn + 255) / 256;    // 391
    const int EB = (Ee + 255) / 256;    // 3125

    k_prep<<<128, 256>>>(fc0_w, Wq, Wk, Wv);                   // 1
    k_fc0<<<GB, 256>>>(x, fc0_b, ln_w, ln_b);                  // 2
    k_zero_red<<<34, 256>>>();                                 // 3
    k_qkv<<<GB, 256>>>(0, bq, bk, bv);                         // 4  <- target profile slot
    k_zcnt<<<NB, 256>>>();                                     // 5
    k_count<<<EB, 256>>>(ei + Ee);                             // 6
    k_rsqk<<<NB, 256>>>();                                     // 7
    k_scan1<<<NB, 256>>>();                                    // 8
    k_scan2<<<1, 512>>>();                                     // 9
    k_scan3<<<NB, 256>>>();                                    // 10
    k_fill<<<EB, 256>>>(ei, ei + Ee);                          // 11
    k_reduce<<<320, 256>>>();                                  // 12
    k_pkvs<<<18, 256>>>();                                     // 13
    k_attnc<<<GB, 256>>>(ln_w + HIDD, ln_b + HIDD);            // 14
    k_zero_red<<<34, 256>>>();                                 // 15
    k_qkv<<<GB, 256>>>(1, bq + HD, bk + HD, bv + HD);          // 16
    k_reduce<<<320, 256>>>();                                  // 17
    k_pkvs<<<18, 256>>>();                                     // 18
    k_attnc<<<GB, 256>>>(ln_w + 2 * HIDD, ln_b + 2 * HIDD);    // 19
    k_fco<<<GB, 256>>>(fco_w, fco_b, out);                     // 20
}